// round 2
// baseline (speedup 1.0000x reference)
#include <cuda_runtime.h>
#include <math_constants.h>

// Problem constants
#define BB   4
#define TT   4096
#define DIN  1024
#define HH   64

#define MROWS (BB * TT)        // 16384

// Scratch for projected q, k, v  (each 4 MB)
__device__ float g_q[MROWS * HH];
__device__ float g_k[MROWS * HH];
__device__ float g_v[MROWS * HH];

// ---------------------------------------------------------------------------
// Kernel 1: projections.  out[m][n] = sum_k x[m][k] * W[n][k] + b[n]
// grid = (MROWS/64, 3), block = 256 (16x16), 4x4 microtile per thread.
// ---------------------------------------------------------------------------
__global__ __launch_bounds__(256) void proj_kernel(
    const float* __restrict__ x,
    const float* __restrict__ Wq, const float* __restrict__ bq,
    const float* __restrict__ Wk, const float* __restrict__ bk,
    const float* __restrict__ Wv, const float* __restrict__ bv)
{
    __shared__ float Xs[32 * 65];   // Xs[k][m], padded
    __shared__ float Ws[32 * 65];   // Ws[k][n], padded

    const float* W;
    const float* bias;
    float* outp;
    if (blockIdx.y == 0)      { W = Wq; bias = bq; outp = g_q; }
    else if (blockIdx.y == 1) { W = Wk; bias = bk; outp = g_k; }
    else                      { W = Wv; bias = bv; outp = g_v; }

    const int m0  = blockIdx.x * 64;
    const int tid = threadIdx.x;
    const int tx  = tid & 15;
    const int ty  = tid >> 4;

    float acc[4][4];
#pragma unroll
    for (int i = 0; i < 4; ++i)
#pragma unroll
        for (int j = 0; j < 4; ++j) acc[i][j] = 0.f;

    for (int k0 = 0; k0 < DIN; k0 += 32) {
        __syncthreads();
#pragma unroll
        for (int e = tid; e < 64 * 32; e += 256) {
            int mm = e >> 5;      // 0..63
            int kk = e & 31;      // 0..31
            Xs[kk * 65 + mm] = x[(size_t)(m0 + mm) * DIN + k0 + kk];
            Ws[kk * 65 + mm] = W[(size_t)mm * DIN + k0 + kk];
        }
        __syncthreads();

#pragma unroll
        for (int kk = 0; kk < 32; ++kk) {
            float a[4], w[4];
#pragma unroll
            for (int i = 0; i < 4; ++i) a[i] = Xs[kk * 65 + ty * 4 + i];
#pragma unroll
            for (int j = 0; j < 4; ++j) w[j] = Ws[kk * 65 + tx * 4 + j];
#pragma unroll
            for (int i = 0; i < 4; ++i)
#pragma unroll
                for (int j = 0; j < 4; ++j) acc[i][j] += a[i] * w[j];
        }
    }

#pragma unroll
    for (int i = 0; i < 4; ++i)
#pragma unroll
        for (int j = 0; j < 4; ++j)
            outp[(size_t)(m0 + ty * 4 + i) * HH + tx * 4 + j] =
                acc[i][j] + bias[tx * 4 + j];
}

// ---------------------------------------------------------------------------
// Kernel 2: causal flash attention.
//   A := k (attention "query" rows i),  Bm := q (keys, cols j),  V := v.
//   out[b,i,h] = sum_{j<=i} softmax_j(k_i . q_j) v[j,h]
// grid = (T/64, B), block = 256 (16x16). Each CTA: 64 rows x 64 head dims.
// S tile (64x64) staged in smem, aliased over the Bs buffer.
// ---------------------------------------------------------------------------
#define TPAD 65
#define SMEM_FLOATS (3 * 64 * TPAD + 3 * 64)

__global__ __launch_bounds__(256) void attn_kernel(float* __restrict__ out)
{
    extern __shared__ float sm[];
    float* As  = sm;                    // 64 x 65  (k rows, fixed)
    float* Bs  = sm + 64 * TPAD;        // 64 x 65  (q tile; aliased as S/P tile)
    float* Vs  = sm + 2 * 64 * TPAD;    // 64 x 65  (v tile)
    float* m_s = sm + 3 * 64 * TPAD;    // 64 running max
    float* l_s = m_s + 64;              // 64 running sum
    float* sc_s= l_s + 64;              // 64 rescale factor

    const int it = (gridDim.x - 1) - blockIdx.x;   // heavy tiles first
    const int b  = blockIdx.y;
    const int tid = threadIdx.x;
    const int tx  = tid & 15;
    const int ty  = tid >> 4;

    const float* kbase = g_k + ((size_t)b * TT + it * 64) * HH;

    // load A tile (k rows)
#pragma unroll
    for (int e = tid; e < 64 * 64; e += 256) {
        int r = e >> 6, h = e & 63;
        As[r * TPAD + h] = kbase[r * HH + h];
    }
    if (tid < 64) { m_s[tid] = -CUDART_INF_F; l_s[tid] = 0.f; }

    float acc[4][4];
#pragma unroll
    for (int i = 0; i < 4; ++i)
#pragma unroll
        for (int j = 0; j < 4; ++j) acc[i][j] = 0.f;

    for (int jt = 0; jt <= it; ++jt) {
        __syncthreads();   // previous iter's reads of Bs(=P) / Vs done

        const float* qb = g_q + ((size_t)b * TT + jt * 64) * HH;
        const float* vb = g_v + ((size_t)b * TT + jt * 64) * HH;
#pragma unroll
        for (int e = tid; e < 64 * 64; e += 256) {
            int r = e >> 6, h = e & 63;
            Bs[r * TPAD + h] = qb[r * HH + h];
            Vs[r * TPAD + h] = vb[r * HH + h];
        }
        __syncthreads();

        // S = A . B^T   (4x4 per thread)
        float s[4][4];
#pragma unroll
        for (int i = 0; i < 4; ++i)
#pragma unroll
            for (int j = 0; j < 4; ++j) s[i][j] = 0.f;

#pragma unroll 8
        for (int h = 0; h < 64; ++h) {
            float a[4], qv[4];
#pragma unroll
            for (int i = 0; i < 4; ++i) a[i]  = As[(ty * 4 + i) * TPAD + h];
#pragma unroll
            for (int j = 0; j < 4; ++j) qv[j] = Bs[(tx * 4 + j) * TPAD + h];
#pragma unroll
            for (int i = 0; i < 4; ++i)
#pragma unroll
                for (int j = 0; j < 4; ++j) s[i][j] += a[i] * qv[j];
        }

        // causal mask on the diagonal tile
        if (jt == it) {
#pragma unroll
            for (int i = 0; i < 4; ++i)
#pragma unroll
                for (int j = 0; j < 4; ++j)
                    if (tx * 4 + j > ty * 4 + i) s[i][j] = -CUDART_INF_F;
        }

        __syncthreads();   // everyone finished reading Bs; safe to overwrite with S
#pragma unroll
        for (int i = 0; i < 4; ++i)
#pragma unroll
            for (int j = 0; j < 4; ++j)
                Bs[(ty * 4 + i) * TPAD + tx * 4 + j] = s[i][j];
        __syncthreads();

        // online softmax: 4 threads per row
        {
            const int row  = tid >> 2;
            const int quad = tid & 3;
            float mx = -CUDART_INF_F;
#pragma unroll
            for (int c = quad * 16; c < quad * 16 + 16; ++c)
                mx = fmaxf(mx, Bs[row * TPAD + c]);
            mx = fmaxf(mx, __shfl_xor_sync(0xffffffffu, mx, 1));
            mx = fmaxf(mx, __shfl_xor_sync(0xffffffffu, mx, 2));

            const float m_old = m_s[row];
            const float m_new = fmaxf(m_old, mx);

            float sum = 0.f;
#pragma unroll
            for (int c = quad * 16; c < quad * 16 + 16; ++c) {
                float p = expf(Bs[row * TPAD + c] - m_new);
                Bs[row * TPAD + c] = p;
                sum += p;
            }
            sum += __shfl_xor_sync(0xffffffffu, sum, 1);
            sum += __shfl_xor_sync(0xffffffffu, sum, 2);

            if (quad == 0) {
                float alpha = expf(m_old - m_new);
                sc_s[row] = alpha;
                l_s[row]  = l_s[row] * alpha + sum;
                m_s[row]  = m_new;
            }
        }
        __syncthreads();

        // rescale accumulators, then O += P . V
        float al[4];
#pragma unroll
        for (int i = 0; i < 4; ++i) al[i] = sc_s[ty * 4 + i];
#pragma unroll
        for (int i = 0; i < 4; ++i)
#pragma unroll
            for (int j = 0; j < 4; ++j) acc[i][j] *= al[i];

#pragma unroll 8
        for (int jj = 0; jj < 64; ++jj) {
            float p[4], vv[4];
#pragma unroll
            for (int i = 0; i < 4; ++i) p[i]  = Bs[(ty * 4 + i) * TPAD + jj];
#pragma unroll
            for (int j = 0; j < 4; ++j) vv[j] = Vs[jj * TPAD + tx * 4 + j];
#pragma unroll
            for (int i = 0; i < 4; ++i)
#pragma unroll
                for (int j = 0; j < 4; ++j) acc[i][j] += p[i] * vv[j];
        }
    }

    __syncthreads();
#pragma unroll
    for (int i = 0; i < 4; ++i) {
        const float inv_l = 1.0f / l_s[ty * 4 + i];
        const size_t rbase = ((size_t)b * TT + it * 64 + ty * 4 + i) * HH;
#pragma unroll
        for (int j = 0; j < 4; ++j)
            out[rbase + tx * 4 + j] = acc[i][j] * inv_l;
    }
}

// ---------------------------------------------------------------------------
extern "C" void kernel_launch(void* const* d_in, const int* in_sizes, int n_in,
                              void* d_out, int out_size)
{
    const float* x  = (const float*)d_in[0];
    const float* Wq = (const float*)d_in[1];
    const float* bq = (const float*)d_in[2];
    const float* Wk = (const float*)d_in[3];
    const float* bk = (const float*)d_in[4];
    const float* Wv = (const float*)d_in[5];
    const float* bv = (const float*)d_in[6];
    float* out = (float*)d_out;

    // Projections: q,k,v = x @ W^T + b
    proj_kernel<<<dim3(MROWS / 64, 3), 256>>>(x, Wq, bq, Wk, bk, Wv, bv);

    // Flash attention
    const int smem_bytes = SMEM_FLOATS * sizeof(float);   // 50,688 B
    cudaFuncSetAttribute(attn_kernel,
                         cudaFuncAttributeMaxDynamicSharedMemorySize,
                         smem_bytes);
    attn_kernel<<<dim3(TT / 64, BB), 256, smem_bytes>>>(out);
}

// round 4
// speedup vs baseline: 3.7788x; 3.7788x over previous
#include <cuda_runtime.h>
#include <cuda_bf16.h>
#include <cstdint>

#define BB 4
#define TT 4096
#define DIN 1024
#define HH 64
#define MROWS (BB*TT)

// bf16 hi/lo split scratch (proj outputs). v stored transposed [b][h][t].
__device__ __nv_bfloat16 g_qh[(size_t)MROWS*HH], g_ql[(size_t)MROWS*HH];
__device__ __nv_bfloat16 g_kh[(size_t)MROWS*HH], g_kl[(size_t)MROWS*HH];
__device__ __nv_bfloat16 g_vth[(size_t)MROWS*HH], g_vtl[(size_t)MROWS*HH];

// ---------------- helpers ----------------
__device__ __forceinline__ void mma_bf16(float* d, const uint32_t* a,
                                         uint32_t b0, uint32_t b1) {
    asm volatile(
        "mma.sync.aligned.m16n8k16.row.col.f32.bf16.bf16.f32 "
        "{%0,%1,%2,%3}, {%4,%5,%6,%7}, {%8,%9}, {%0,%1,%2,%3};"
        : "+f"(d[0]), "+f"(d[1]), "+f"(d[2]), "+f"(d[3])
        : "r"(a[0]), "r"(a[1]), "r"(a[2]), "r"(a[3]), "r"(b0), "r"(b1));
}

// split (x,y) into packed bf16x2 hi and lo parts (x in lower half)
__device__ __forceinline__ void split_pair(float x, float y,
                                           uint32_t& h, uint32_t& l) {
    __nv_bfloat162 hv = __floats2bfloat162_rn(x, y);
    float hx = __bfloat162float(hv.x);
    float hy = __bfloat162float(hv.y);
    __nv_bfloat162 lv = __floats2bfloat162_rn(x - hx, y - hy);
    h = *reinterpret_cast<uint32_t*>(&hv);
    l = *reinterpret_cast<uint32_t*>(&lv);
}

// SMEM tile geometry: 64 rows x 64 bf16, row stride 144 bytes (72 bf16)
#define RS 144

// ============================================================================
// Projection: out = X @ W^T + b via mma.sync, bf16 2-way split (3 products).
// grid = (128, 3); CTA = 256 thr = 8 warps x 16 rows = 128 rows; N = 64.
// ============================================================================
#define PROJ_SMEM (128*RS*2 + 64*RS*2)   // Xh,Xl,Wh,Wl = 55296 B

__global__ __launch_bounds__(256, 1) void proj_kernel(
    const float* __restrict__ x,
    const float* __restrict__ Wq, const float* __restrict__ bq,
    const float* __restrict__ Wk, const float* __restrict__ bk,
    const float* __restrict__ Wv, const float* __restrict__ bv)
{
    extern __shared__ char smp[];
    __shared__ float s_bias[64];
    char* Xh = smp;
    char* Xl = smp + 128*RS;
    char* Wh = smp + 256*RS;
    char* Wl = smp + 256*RS + 64*RS;

    const int tid = threadIdx.x;
    const int wid = tid >> 5, lane = tid & 31;
    const int g = lane >> 2, tg = lane & 3;
    const int m0 = blockIdx.x * 128;
    const int my = blockIdx.y;

    const float* W    = (my == 0) ? Wq : (my == 1) ? Wk : Wv;
    const float* bias = (my == 0) ? bq : (my == 1) ? bk : bv;
    if (tid < 64) s_bias[tid] = bias[tid];

    float acc[8][4];
#pragma unroll
    for (int n = 0; n < 8; ++n)
#pragma unroll
        for (int q = 0; q < 4; ++q) acc[n][q] = 0.f;

    for (int kc = 0; kc < 16; ++kc) {
        const int k0 = kc * 64;
        __syncthreads();
        // stage X chunk 128x64 (split)
#pragma unroll
        for (int i = tid; i < 2048; i += 256) {
            int r = i >> 4, c4 = i & 15;
            float4 v = *(const float4*)(x + (size_t)(m0 + r)*DIN + k0 + c4*4);
            uint32_t h0, l0, h1, l1;
            split_pair(v.x, v.y, h0, l0);
            split_pair(v.z, v.w, h1, l1);
            *(uint2*)(Xh + r*RS + c4*8) = make_uint2(h0, h1);
            *(uint2*)(Xl + r*RS + c4*8) = make_uint2(l0, l1);
        }
        // stage W chunk 64x64 (split)
#pragma unroll
        for (int i = tid; i < 1024; i += 256) {
            int r = i >> 4, c4 = i & 15;
            float4 v = *(const float4*)(W + (size_t)r*DIN + k0 + c4*4);
            uint32_t h0, l0, h1, l1;
            split_pair(v.x, v.y, h0, l0);
            split_pair(v.z, v.w, h1, l1);
            *(uint2*)(Wh + r*RS + c4*8) = make_uint2(h0, h1);
            *(uint2*)(Wl + r*RS + c4*8) = make_uint2(l0, l1);
        }
        __syncthreads();

        const int ra = wid*16 + g;
#pragma unroll
        for (int ks = 0; ks < 4; ++ks) {
            const int co = (16*ks + 2*tg)*2;
            uint32_t ah[4], al[4];
            ah[0] = *(const uint32_t*)(Xh + ra*RS + co);
            ah[1] = *(const uint32_t*)(Xh + (ra+8)*RS + co);
            ah[2] = *(const uint32_t*)(Xh + ra*RS + co + 16);
            ah[3] = *(const uint32_t*)(Xh + (ra+8)*RS + co + 16);
            al[0] = *(const uint32_t*)(Xl + ra*RS + co);
            al[1] = *(const uint32_t*)(Xl + (ra+8)*RS + co);
            al[2] = *(const uint32_t*)(Xl + ra*RS + co + 16);
            al[3] = *(const uint32_t*)(Xl + (ra+8)*RS + co + 16);
#pragma unroll
            for (int n = 0; n < 8; ++n) {
                const char* w0 = Wh + (8*n + g)*RS + co;
                const char* w1 = Wl + (8*n + g)*RS + co;
                uint32_t bh0 = *(const uint32_t*)w0;
                uint32_t bh1 = *(const uint32_t*)(w0 + 16);
                uint32_t bl0 = *(const uint32_t*)w1;
                uint32_t bl1 = *(const uint32_t*)(w1 + 16);
                mma_bf16(acc[n], ah, bh0, bh1);
                mma_bf16(acc[n], al, bh0, bh1);
                mma_bf16(acc[n], ah, bl0, bl1);
            }
        }
    }

    // epilogue: add bias, split, store
    const int rA = m0 + wid*16 + g;
    const int rB = rA + 8;
#pragma unroll
    for (int n = 0; n < 8; ++n) {
        const int col = 8*n + 2*tg;
        float v0 = acc[n][0] + s_bias[col];
        float v1 = acc[n][1] + s_bias[col+1];
        float v2 = acc[n][2] + s_bias[col];
        float v3 = acc[n][3] + s_bias[col+1];
        if (my < 2) {
            uint32_t h01, l01, h23, l23;
            split_pair(v0, v1, h01, l01);
            split_pair(v2, v3, h23, l23);
            __nv_bfloat16* oh = (my == 0) ? g_qh : g_kh;
            __nv_bfloat16* ol = (my == 0) ? g_ql : g_kl;
            *(uint32_t*)(oh + (size_t)rA*64 + col) = h01;
            *(uint32_t*)(ol + (size_t)rA*64 + col) = l01;
            *(uint32_t*)(oh + (size_t)rB*64 + col) = h23;
            *(uint32_t*)(ol + (size_t)rB*64 + col) = l23;
        } else {
            // v transposed: vt[(b*64 + h)*4096 + t]
            const int bA = rA >> 12, tA = rA & 4095;
            const int bB = rB >> 12, tB = rB & 4095;
            __nv_bfloat16 h;
            h = __float2bfloat16_rn(v0);
            g_vth[(size_t)(bA*64 + col  )*4096 + tA] = h;
            g_vtl[(size_t)(bA*64 + col  )*4096 + tA] = __float2bfloat16_rn(v0 - __bfloat162float(h));
            h = __float2bfloat16_rn(v1);
            g_vth[(size_t)(bA*64 + col+1)*4096 + tA] = h;
            g_vtl[(size_t)(bA*64 + col+1)*4096 + tA] = __float2bfloat16_rn(v1 - __bfloat162float(h));
            h = __float2bfloat16_rn(v2);
            g_vth[(size_t)(bB*64 + col  )*4096 + tB] = h;
            g_vtl[(size_t)(bB*64 + col  )*4096 + tB] = __float2bfloat16_rn(v2 - __bfloat162float(h));
            h = __float2bfloat16_rn(v3);
            g_vth[(size_t)(bB*64 + col+1)*4096 + tB] = h;
            g_vtl[(size_t)(bB*64 + col+1)*4096 + tB] = __float2bfloat16_rn(v3 - __bfloat162float(h));
        }
    }
}

// ============================================================================
// Attention: grid = 128 CTAs; CTA = 2 independent groups of 4 warps.
// Group 0 handles i-tile c, group 1 handles i-tile 63-c (64 rows each)
// => uniform 65 j-tile iterations per CTA. No online softmax (linear sums).
// ============================================================================
#define GRP_SMEM (4*64*RS)               // Qh,Ql,Vth,Vtl per group = 36864
#define ATTN_SMEM (2*GRP_SMEM)           // 73728

__global__ __launch_bounds__(256, 1) void attn_kernel(float* __restrict__ out)
{
    extern __shared__ char smp[];
    const int tid = threadIdx.x;
    const int grp = tid >> 7;
    const int lt  = tid & 127;
    const int lw  = (tid >> 5) & 3;
    const int lane = tid & 31;
    const int g  = lane >> 2, tg = lane & 3;

    const int b  = blockIdx.x >> 5;
    const int c  = blockIdx.x & 31;
    const int rb = grp ? (63 - c) : c;
    const int i0 = rb * 64;
    const int bid = grp + 1;

    char* gb = smp + grp * GRP_SMEM;
    char* Qh = gb;
    char* Ql = gb + 64*RS;
    char* Vh = gb + 128*RS;
    char* Vl = gb + 192*RS;

    // persistent K fragments for this warp's 16 rows
    const int rowA = i0 + lw*16 + g;      // local (per-batch) row index
    uint32_t kh[4][4], kl[4][4];
    {
        const size_t r0 = (size_t)(b*4096 + rowA) * 64;
        const uint32_t* ph0 = (const uint32_t*)(g_kh + r0);
        const uint32_t* ph1 = (const uint32_t*)(g_kh + r0 + 8*64);
        const uint32_t* pl0 = (const uint32_t*)(g_kl + r0);
        const uint32_t* pl1 = (const uint32_t*)(g_kl + r0 + 8*64);
#pragma unroll
        for (int ks = 0; ks < 4; ++ks) {
            kh[ks][0] = ph0[tg + 8*ks];     kh[ks][1] = ph1[tg + 8*ks];
            kh[ks][2] = ph0[tg + 8*ks + 4]; kh[ks][3] = ph1[tg + 8*ks + 4];
            kl[ks][0] = pl0[tg + 8*ks];     kl[ks][1] = pl1[tg + 8*ks];
            kl[ks][2] = pl0[tg + 8*ks + 4]; kl[ks][3] = pl1[tg + 8*ks + 4];
        }
    }

    float o[8][4];
#pragma unroll
    for (int n = 0; n < 8; ++n)
#pragma unroll
        for (int q = 0; q < 4; ++q) o[n][q] = 0.f;
    float ellA = 0.f, ellB = 0.f;

    for (int jt = 0; jt <= rb; ++jt) {
        const int j0 = jt * 64;
        asm volatile("bar.sync %0, 128;" :: "r"(bid) : "memory");
        // stage Qh,Ql (64x64 row-major) and Vth,Vtl (64x64, [h][j])
#pragma unroll
        for (int i = lt; i < 2048; i += 128) {
            const int comp = i >> 9;
            const int idx = i & 511;
            const int r = idx >> 3, c8 = idx & 7;
            const uint4* src;
            if (comp == 0)
                src = (const uint4*)(g_qh + (size_t)(b*4096 + j0 + r)*64 + c8*8);
            else if (comp == 1)
                src = (const uint4*)(g_ql + (size_t)(b*4096 + j0 + r)*64 + c8*8);
            else if (comp == 2)
                src = (const uint4*)(g_vth + (size_t)(b*64 + r)*4096 + j0 + c8*8);
            else
                src = (const uint4*)(g_vtl + (size_t)(b*64 + r)*4096 + j0 + c8*8);
            *(uint4*)(gb + comp*(64*RS) + r*RS + c8*16) = *src;
        }
        asm volatile("bar.sync %0, 128;" :: "r"(bid) : "memory");

        // ---- S = K . Q^T  (16 x 64 per warp) ----
        float s[8][4];
#pragma unroll
        for (int n = 0; n < 8; ++n)
#pragma unroll
            for (int q = 0; q < 4; ++q) s[n][q] = 0.f;

#pragma unroll
        for (int ks = 0; ks < 4; ++ks) {
            const int co = (16*ks + 2*tg)*2;
#pragma unroll
            for (int n = 0; n < 8; ++n) {
                const char* q0 = Qh + (8*n + g)*RS + co;
                const char* q1 = Ql + (8*n + g)*RS + co;
                uint32_t bh0 = *(const uint32_t*)q0;
                uint32_t bh1 = *(const uint32_t*)(q0 + 16);
                uint32_t bl0 = *(const uint32_t*)q1;
                uint32_t bl1 = *(const uint32_t*)(q1 + 16);
                mma_bf16(s[n], kh[ks], bh0, bh1);
                mma_bf16(s[n], kl[ks], bh0, bh1);
                mma_bf16(s[n], kh[ks], bl0, bl1);
            }
        }

        // ---- P = exp(S), mask, ell, pack into A-fragments ----
        uint32_t pha[4][4], pla[4][4];
        const bool diag = (jt == rb);
#pragma unroll
        for (int n = 0; n < 8; ++n) {
            float p0 = __expf(s[n][0]);
            float p1 = __expf(s[n][1]);
            float p2 = __expf(s[n][2]);
            float p3 = __expf(s[n][3]);
            if (diag) {
                const int col = j0 + 8*n + 2*tg;
                if (col   > rowA)     p0 = 0.f;
                if (col+1 > rowA)     p1 = 0.f;
                if (col   > rowA + 8) p2 = 0.f;
                if (col+1 > rowA + 8) p3 = 0.f;
            }
            ellA += p0 + p1;
            ellB += p2 + p3;
            uint32_t h01, l01, h23, l23;
            split_pair(p0, p1, h01, l01);
            split_pair(p2, p3, h23, l23);
            const int t = n >> 1;
            if ((n & 1) == 0) {
                pha[t][0] = h01; pha[t][1] = h23;
                pla[t][0] = l01; pla[t][1] = l23;
            } else {
                pha[t][2] = h01; pha[t][3] = h23;
                pla[t][2] = l01; pla[t][3] = l23;
            }
        }

        // ---- O += P . V ----
#pragma unroll
        for (int t = 0; t < 4; ++t) {
            const int co = (16*t + 2*tg)*2;
#pragma unroll
            for (int n = 0; n < 8; ++n) {
                const char* v0 = Vh + (8*n + g)*RS + co;
                const char* v1 = Vl + (8*n + g)*RS + co;
                uint32_t bh0 = *(const uint32_t*)v0;
                uint32_t bh1 = *(const uint32_t*)(v0 + 16);
                uint32_t bl0 = *(const uint32_t*)v1;
                uint32_t bl1 = *(const uint32_t*)(v1 + 16);
                mma_bf16(o[n], pha[t], bh0, bh1);
                mma_bf16(o[n], pla[t], bh0, bh1);
                mma_bf16(o[n], pha[t], bl0, bl1);
            }
        }
    }

    // reduce row sums across the 4 threads covering each row
    ellA += __shfl_xor_sync(0xffffffffu, ellA, 1);
    ellA += __shfl_xor_sync(0xffffffffu, ellA, 2);
    ellB += __shfl_xor_sync(0xffffffffu, ellB, 1);
    ellB += __shfl_xor_sync(0xffffffffu, ellB, 2);
    const float invA = 1.0f / ellA;
    const float invB = 1.0f / ellB;

    const size_t orA = (size_t)(b*4096 + rowA) * 64;
    const size_t orB = orA + 8*64;
#pragma unroll
    for (int n = 0; n < 8; ++n) {
        const int col = 8*n + 2*tg;
        float2 vA = make_float2(o[n][0]*invA, o[n][1]*invA);
        float2 vB = make_float2(o[n][2]*invB, o[n][3]*invB);
        *(float2*)(out + orA + col) = vA;
        *(float2*)(out + orB + col) = vB;
    }
}

// ============================================================================
extern "C" void kernel_launch(void* const* d_in, const int* in_sizes, int n_in,
                              void* d_out, int out_size)
{
    const float* x  = (const float*)d_in[0];
    const float* Wq = (const float*)d_in[1];
    const float* bq = (const float*)d_in[2];
    const float* Wk = (const float*)d_in[3];
    const float* bk = (const float*)d_in[4];
    const float* Wv = (const float*)d_in[5];
    const float* bv = (const float*)d_in[6];
    float* out = (float*)d_out;

    cudaFuncSetAttribute(proj_kernel, cudaFuncAttributeMaxDynamicSharedMemorySize, PROJ_SMEM);
    cudaFuncSetAttribute(attn_kernel, cudaFuncAttributeMaxDynamicSharedMemorySize, ATTN_SMEM);

    proj_kernel<<<dim3(128, 3), 256, PROJ_SMEM>>>(x, Wq, bq, Wk, bk, Wv, bv);
    attn_kernel<<<dim3(BB * 32), 256, ATTN_SMEM>>>(out);
}

// round 5
// speedup vs baseline: 3.8258x; 1.0124x over previous
#include <cuda_runtime.h>
#include <cuda_bf16.h>
#include <cstdint>

#define BB 4
#define TT 4096
#define DIN 1024
#define HH 64
#define MROWS (BB*TT)

// bf16 hi/lo split scratch
__device__ __nv_bfloat16 g_qh[(size_t)MROWS*HH], g_ql[(size_t)MROWS*HH];
__device__ __nv_bfloat16 g_kh[(size_t)MROWS*HH], g_kl[(size_t)MROWS*HH];
__device__ __nv_bfloat16 g_vth[(size_t)MROWS*HH], g_vtl[(size_t)MROWS*HH]; // [b][h][t]
// pre-converted inputs
__device__ __nv_bfloat16 g_xh[(size_t)MROWS*DIN], g_xl[(size_t)MROWS*DIN];
__device__ __nv_bfloat16 g_wh[3*HH*DIN], g_wl[3*HH*DIN];   // [set][n][k]

// ---------------- helpers ----------------
__device__ __forceinline__ void mma_bf16(float* d, const uint32_t* a,
                                         uint32_t b0, uint32_t b1) {
    asm volatile(
        "mma.sync.aligned.m16n8k16.row.col.f32.bf16.bf16.f32 "
        "{%0,%1,%2,%3}, {%4,%5,%6,%7}, {%8,%9}, {%0,%1,%2,%3};"
        : "+f"(d[0]), "+f"(d[1]), "+f"(d[2]), "+f"(d[3])
        : "r"(a[0]), "r"(a[1]), "r"(a[2]), "r"(a[3]), "r"(b0), "r"(b1));
}

__device__ __forceinline__ void split_pair(float x, float y,
                                           uint32_t& h, uint32_t& l) {
    __nv_bfloat162 hv = __floats2bfloat162_rn(x, y);
    float hx = __bfloat162float(hv.x);
    float hy = __bfloat162float(hv.y);
    __nv_bfloat162 lv = __floats2bfloat162_rn(x - hx, y - hy);
    h = *reinterpret_cast<uint32_t*>(&hv);
    l = *reinterpret_cast<uint32_t*>(&lv);
}

__device__ __forceinline__ uint32_t smem_u32(const void* p) {
    uint32_t a;
    asm("{ .reg .u64 t; cvta.to.shared.u64 t, %1; cvt.u32.u64 %0, t; }"
        : "=r"(a) : "l"(p));
    return a;
}

__device__ __forceinline__ void cpa16(uint32_t dst, const void* src) {
    asm volatile("cp.async.cg.shared.global [%0], [%1], 16;"
                 :: "r"(dst), "l"(src) : "memory");
}
#define CPA_COMMIT() asm volatile("cp.async.commit_group;" ::: "memory")
#define CPA_WAIT0()  asm volatile("cp.async.wait_group 0;" ::: "memory")

#define RS 144   // smem row stride in bytes (64 bf16 data + pad)

// ============================================================================
// Pre-convert: X -> (g_xh, g_xl), W -> (g_wh, g_wl)
// ============================================================================
__global__ __launch_bounds__(256) void convert_kernel(
    const float* __restrict__ x,
    const float* __restrict__ Wq, const float* __restrict__ Wk,
    const float* __restrict__ Wv)
{
    const size_t tid0 = (size_t)blockIdx.x * 256 + threadIdx.x;
    const size_t stride = (size_t)gridDim.x * 256;
    const size_t NX = (size_t)MROWS * DIN / 4;
    for (size_t t = tid0; t < NX; t += stride) {
        float4 v = ((const float4*)x)[t];
        uint32_t h0, l0, h1, l1;
        split_pair(v.x, v.y, h0, l0);
        split_pair(v.z, v.w, h1, l1);
        ((uint2*)g_xh)[t] = make_uint2(h0, h1);
        ((uint2*)g_xl)[t] = make_uint2(l0, l1);
    }
    const size_t NW = (size_t)HH * DIN / 4;   // per set
    for (size_t t = tid0; t < 3 * NW; t += stride) {
        const int set = (int)(t / NW);
        const size_t o = t - (size_t)set * NW;
        const float* W = (set == 0) ? Wq : (set == 1) ? Wk : Wv;
        float4 v = ((const float4*)W)[o];
        uint32_t h0, l0, h1, l1;
        split_pair(v.x, v.y, h0, l0);
        split_pair(v.z, v.w, h1, l1);
        ((uint2*)g_wh)[t] = make_uint2(h0, h1);
        ((uint2*)g_wl)[t] = make_uint2(l0, l1);
    }
}

// ============================================================================
// Projection: out = X @ W^T + b. grid=(128,3), 256 thr.
// cp.async double-buffered staging of pre-split X/W chunks (K-chunk = 64).
// ============================================================================
#define P_XH 0
#define P_XL (128*RS)
#define P_WH (256*RS)
#define P_WL (256*RS + 64*RS)
#define PBUF (384*RS)            // 55296 per buffer
#define PROJ_SMEM (2*PBUF)       // 110592

__global__ __launch_bounds__(256, 1) void proj_kernel(
    const float* __restrict__ bq, const float* __restrict__ bk,
    const float* __restrict__ bv)
{
    extern __shared__ char smp[];
    __shared__ float s_bias[64];
    const uint32_t sbase = smem_u32(smp);

    const int tid = threadIdx.x;
    const int wid = tid >> 5, lane = tid & 31;
    const int g = lane >> 2, tg = lane & 3;
    const int m0 = blockIdx.x * 128;
    const int my = blockIdx.y;

    const float* bias = (my == 0) ? bq : (my == 1) ? bk : bv;
    if (tid < 64) s_bias[tid] = bias[tid];

    const size_t wset = (size_t)my * HH * DIN;

    // stage chunk kc into buffer bi: 3072 16B units / 256 thr = 12 each
    auto stage = [&](int kc, int bi) {
        const int k0 = kc * 64;
        const uint32_t bb = sbase + bi * PBUF;
#pragma unroll
        for (int u = tid; u < 3072; u += 256) {
            uint32_t dst; const void* src;
            if (u < 2048) {
                const int comp = u >> 10;          // 0=Xh,1=Xl
                const int idx = u & 1023;
                const int r = idx >> 3, c8 = idx & 7;
                const __nv_bfloat16* gsrc = comp ? g_xl : g_xh;
                src = gsrc + (size_t)(m0 + r) * DIN + k0 + c8 * 8;
                dst = bb + (comp ? P_XL : P_XH) + r * RS + c8 * 16;
            } else {
                const int comp = (u - 2048) >> 9;  // 0=Wh,1=Wl
                const int idx = (u - 2048) & 511;
                const int r = idx >> 3, c8 = idx & 7;
                const __nv_bfloat16* gsrc = comp ? g_wl : g_wh;
                src = gsrc + wset + (size_t)r * DIN + k0 + c8 * 8;
                dst = bb + (comp ? P_WL : P_WH) + r * RS + c8 * 16;
            }
            cpa16(dst, src);
        }
        CPA_COMMIT();
    };

    float acc[8][4];
#pragma unroll
    for (int n = 0; n < 8; ++n)
#pragma unroll
        for (int q = 0; q < 4; ++q) acc[n][q] = 0.f;

    stage(0, 0);
    for (int kc = 0; kc < 16; ++kc) {
        CPA_WAIT0();
        __syncthreads();
        if (kc < 15) stage(kc + 1, (kc + 1) & 1);

        const char* Xh = smp + (kc & 1) * PBUF + P_XH;
        const char* Xl = smp + (kc & 1) * PBUF + P_XL;
        const char* Wh = smp + (kc & 1) * PBUF + P_WH;
        const char* Wl = smp + (kc & 1) * PBUF + P_WL;

        const int ra = wid * 16 + g;
#pragma unroll
        for (int ks = 0; ks < 4; ++ks) {
            const int co = (16 * ks + 2 * tg) * 2;
            uint32_t ah[4], al[4];
            ah[0] = *(const uint32_t*)(Xh + ra * RS + co);
            ah[1] = *(const uint32_t*)(Xh + (ra + 8) * RS + co);
            ah[2] = *(const uint32_t*)(Xh + ra * RS + co + 16);
            ah[3] = *(const uint32_t*)(Xh + (ra + 8) * RS + co + 16);
            al[0] = *(const uint32_t*)(Xl + ra * RS + co);
            al[1] = *(const uint32_t*)(Xl + (ra + 8) * RS + co);
            al[2] = *(const uint32_t*)(Xl + ra * RS + co + 16);
            al[3] = *(const uint32_t*)(Xl + (ra + 8) * RS + co + 16);
#pragma unroll
            for (int n = 0; n < 8; ++n) {
                const char* w0 = Wh + (8 * n + g) * RS + co;
                const char* w1 = Wl + (8 * n + g) * RS + co;
                uint32_t bh0 = *(const uint32_t*)w0;
                uint32_t bh1 = *(const uint32_t*)(w0 + 16);
                uint32_t bl0 = *(const uint32_t*)w1;
                uint32_t bl1 = *(const uint32_t*)(w1 + 16);
                mma_bf16(acc[n], ah, bh0, bh1);
                mma_bf16(acc[n], al, bh0, bh1);
                mma_bf16(acc[n], ah, bl0, bl1);
            }
        }
        __syncthreads();
    }

    // epilogue
    const int rA = m0 + wid * 16 + g;
    const int rB = rA + 8;
#pragma unroll
    for (int n = 0; n < 8; ++n) {
        const int col = 8 * n + 2 * tg;
        float v0 = acc[n][0] + s_bias[col];
        float v1 = acc[n][1] + s_bias[col + 1];
        float v2 = acc[n][2] + s_bias[col];
        float v3 = acc[n][3] + s_bias[col + 1];
        if (my < 2) {
            uint32_t h01, l01, h23, l23;
            split_pair(v0, v1, h01, l01);
            split_pair(v2, v3, h23, l23);
            __nv_bfloat16* oh = (my == 0) ? g_qh : g_kh;
            __nv_bfloat16* ol = (my == 0) ? g_ql : g_kl;
            *(uint32_t*)(oh + (size_t)rA * 64 + col) = h01;
            *(uint32_t*)(ol + (size_t)rA * 64 + col) = l01;
            *(uint32_t*)(oh + (size_t)rB * 64 + col) = h23;
            *(uint32_t*)(ol + (size_t)rB * 64 + col) = l23;
        } else {
            const int bA = rA >> 12, tA = rA & 4095;
            const int bB = rB >> 12, tB = rB & 4095;
            __nv_bfloat16 h;
            h = __float2bfloat16_rn(v0);
            g_vth[(size_t)(bA*64 + col  )*4096 + tA] = h;
            g_vtl[(size_t)(bA*64 + col  )*4096 + tA] = __float2bfloat16_rn(v0 - __bfloat162float(h));
            h = __float2bfloat16_rn(v1);
            g_vth[(size_t)(bA*64 + col+1)*4096 + tA] = h;
            g_vtl[(size_t)(bA*64 + col+1)*4096 + tA] = __float2bfloat16_rn(v1 - __bfloat162float(h));
            h = __float2bfloat16_rn(v2);
            g_vth[(size_t)(bB*64 + col  )*4096 + tB] = h;
            g_vtl[(size_t)(bB*64 + col  )*4096 + tB] = __float2bfloat16_rn(v2 - __bfloat162float(h));
            h = __float2bfloat16_rn(v3);
            g_vth[(size_t)(bB*64 + col+1)*4096 + tB] = h;
            g_vtl[(size_t)(bB*64 + col+1)*4096 + tB] = __float2bfloat16_rn(v3 - __bfloat162float(h));
        }
    }
}

// ============================================================================
// Attention: 128 CTAs; 2 groups of 4 warps per CTA (i-tiles c and 63-c).
// cp.async double-buffered Q/V staging; linear softmax (no max subtraction).
// ============================================================================
#define CBUF (4*64*RS)                 // Qh,Ql,Vh,Vl = 36864 per buffer
#define GRP_SMEM (2*CBUF)              // double buffered
#define ATTN_SMEM (2*GRP_SMEM)         // 147456

__global__ __launch_bounds__(256, 1) void attn_kernel(float* __restrict__ out)
{
    extern __shared__ char smp[];
    const uint32_t sbase = smem_u32(smp);
    const int tid = threadIdx.x;
    const int grp = tid >> 7;
    const int lt  = tid & 127;
    const int lw  = (tid >> 5) & 3;
    const int lane = tid & 31;
    const int g  = lane >> 2, tg = lane & 3;

    const int b  = blockIdx.x >> 5;
    const int c  = blockIdx.x & 31;
    const int rb = grp ? (63 - c) : c;
    const int i0 = rb * 64;
    const int bid = grp + 1;

    const uint32_t gb_u = sbase + grp * GRP_SMEM;
    char* gb_p = smp + grp * GRP_SMEM;

    auto stage = [&](int jt, int bi) {
        const int j0 = jt * 64;
        const uint32_t bb = gb_u + bi * CBUF;
#pragma unroll
        for (int i = lt; i < 2048; i += 128) {
            const int comp = i >> 9;
            const int idx = i & 511;
            const int r = idx >> 3, c8 = idx & 7;
            const void* src;
            if (comp == 0)
                src = g_qh + (size_t)(b * 4096 + j0 + r) * 64 + c8 * 8;
            else if (comp == 1)
                src = g_ql + (size_t)(b * 4096 + j0 + r) * 64 + c8 * 8;
            else if (comp == 2)
                src = g_vth + (size_t)(b * 64 + r) * 4096 + j0 + c8 * 8;
            else
                src = g_vtl + (size_t)(b * 64 + r) * 4096 + j0 + c8 * 8;
            cpa16(bb + comp * (64 * RS) + r * RS + c8 * 16, src);
        }
        CPA_COMMIT();
    };

    // persistent K fragments
    const int rowA = i0 + lw * 16 + g;
    uint32_t kh[4][4], kl[4][4];
    {
        const size_t r0 = (size_t)(b * 4096 + rowA) * 64;
        const uint32_t* ph0 = (const uint32_t*)(g_kh + r0);
        const uint32_t* ph1 = (const uint32_t*)(g_kh + r0 + 8 * 64);
        const uint32_t* pl0 = (const uint32_t*)(g_kl + r0);
        const uint32_t* pl1 = (const uint32_t*)(g_kl + r0 + 8 * 64);
#pragma unroll
        for (int ks = 0; ks < 4; ++ks) {
            kh[ks][0] = ph0[tg + 8*ks];     kh[ks][1] = ph1[tg + 8*ks];
            kh[ks][2] = ph0[tg + 8*ks + 4]; kh[ks][3] = ph1[tg + 8*ks + 4];
            kl[ks][0] = pl0[tg + 8*ks];     kl[ks][1] = pl1[tg + 8*ks];
            kl[ks][2] = pl0[tg + 8*ks + 4]; kl[ks][3] = pl1[tg + 8*ks + 4];
        }
    }

    float o[8][4];
#pragma unroll
    for (int n = 0; n < 8; ++n)
#pragma unroll
        for (int q = 0; q < 4; ++q) o[n][q] = 0.f;
    float ellA = 0.f, ellB = 0.f;

    stage(0, 0);
    for (int jt = 0; jt <= rb; ++jt) {
        const int j0 = jt * 64;
        CPA_WAIT0();
        asm volatile("bar.sync %0, 128;" :: "r"(bid) : "memory");
        if (jt < rb) stage(jt + 1, (jt + 1) & 1);

        const char* bp = gb_p + (jt & 1) * CBUF;
        const char* Qh = bp;
        const char* Ql = bp + 64 * RS;
        const char* Vh = bp + 128 * RS;
        const char* Vl = bp + 192 * RS;

        // ---- S = K . Q^T ----
        float s[8][4];
#pragma unroll
        for (int n = 0; n < 8; ++n)
#pragma unroll
            for (int q = 0; q < 4; ++q) s[n][q] = 0.f;

#pragma unroll
        for (int ks = 0; ks < 4; ++ks) {
            const int co = (16 * ks + 2 * tg) * 2;
#pragma unroll
            for (int n = 0; n < 8; ++n) {
                const char* q0 = Qh + (8 * n + g) * RS + co;
                const char* q1 = Ql + (8 * n + g) * RS + co;
                uint32_t bh0 = *(const uint32_t*)q0;
                uint32_t bh1 = *(const uint32_t*)(q0 + 16);
                uint32_t bl0 = *(const uint32_t*)q1;
                uint32_t bl1 = *(const uint32_t*)(q1 + 16);
                mma_bf16(s[n], kh[ks], bh0, bh1);
                mma_bf16(s[n], kl[ks], bh0, bh1);
                mma_bf16(s[n], kh[ks], bl0, bl1);
            }
        }

        // ---- P = exp(S), mask, ell, pack ----
        uint32_t pha[4][4], pla[4][4];
        const bool diag = (jt == rb);
#pragma unroll
        for (int n = 0; n < 8; ++n) {
            float p0 = __expf(s[n][0]);
            float p1 = __expf(s[n][1]);
            float p2 = __expf(s[n][2]);
            float p3 = __expf(s[n][3]);
            if (diag) {
                const int col = j0 + 8 * n + 2 * tg;
                if (col     > rowA)     p0 = 0.f;
                if (col + 1 > rowA)     p1 = 0.f;
                if (col     > rowA + 8) p2 = 0.f;
                if (col + 1 > rowA + 8) p3 = 0.f;
            }
            ellA += p0 + p1;
            ellB += p2 + p3;
            uint32_t h01, l01, h23, l23;
            split_pair(p0, p1, h01, l01);
            split_pair(p2, p3, h23, l23);
            const int t = n >> 1;
            if ((n & 1) == 0) {
                pha[t][0] = h01; pha[t][1] = h23;
                pla[t][0] = l01; pla[t][1] = l23;
            } else {
                pha[t][2] = h01; pha[t][3] = h23;
                pla[t][2] = l01; pla[t][3] = l23;
            }
        }

        // ---- O += P . V ----
#pragma unroll
        for (int t = 0; t < 4; ++t) {
            const int co = (16 * t + 2 * tg) * 2;
#pragma unroll
            for (int n = 0; n < 8; ++n) {
                const char* v0 = Vh + (8 * n + g) * RS + co;
                const char* v1 = Vl + (8 * n + g) * RS + co;
                uint32_t bh0 = *(const uint32_t*)v0;
                uint32_t bh1 = *(const uint32_t*)(v0 + 16);
                uint32_t bl0 = *(const uint32_t*)v1;
                uint32_t bl1 = *(const uint32_t*)(v1 + 16);
                mma_bf16(o[n], pha[t], bh0, bh1);
                mma_bf16(o[n], pla[t], bh0, bh1);
                mma_bf16(o[n], pha[t], bl0, bl1);
            }
        }
    }

    ellA += __shfl_xor_sync(0xffffffffu, ellA, 1);
    ellA += __shfl_xor_sync(0xffffffffu, ellA, 2);
    ellB += __shfl_xor_sync(0xffffffffu, ellB, 1);
    ellB += __shfl_xor_sync(0xffffffffu, ellB, 2);
    const float invA = 1.0f / ellA;
    const float invB = 1.0f / ellB;

    const size_t orA = (size_t)(b * 4096 + rowA) * 64;
    const size_t orB = orA + 8 * 64;
#pragma unroll
    for (int n = 0; n < 8; ++n) {
        const int col = 8 * n + 2 * tg;
        *(float2*)(out + orA + col) = make_float2(o[n][0]*invA, o[n][1]*invA);
        *(float2*)(out + orB + col) = make_float2(o[n][2]*invB, o[n][3]*invB);
    }
}

// ============================================================================
extern "C" void kernel_launch(void* const* d_in, const int* in_sizes, int n_in,
                              void* d_out, int out_size)
{
    const float* x  = (const float*)d_in[0];
    const float* Wq = (const float*)d_in[1];
    const float* bq = (const float*)d_in[2];
    const float* Wk = (const float*)d_in[3];
    const float* bk = (const float*)d_in[4];
    const float* Wv = (const float*)d_in[5];
    const float* bv = (const float*)d_in[6];
    float* out = (float*)d_out;

    cudaFuncSetAttribute(proj_kernel, cudaFuncAttributeMaxDynamicSharedMemorySize, PROJ_SMEM);
    cudaFuncSetAttribute(attn_kernel, cudaFuncAttributeMaxDynamicSharedMemorySize, ATTN_SMEM);

    convert_kernel<<<1024, 256>>>(x, Wq, Wk, Wv);
    proj_kernel<<<dim3(128, 3), 256, PROJ_SMEM>>>(bq, bk, bv);
    attn_kernel<<<dim3(BB * 32), 256, ATTN_SMEM>>>(out);
}

// round 6
// speedup vs baseline: 4.2680x; 1.1156x over previous
#include <cuda_runtime.h>
#include <cuda_bf16.h>
#include <cstdint>

#define BB 4
#define TT 4096
#define DIN 1024
#define HH 64
#define MROWS (BB*TT)

// bf16 hi/lo split scratch
__device__ __nv_bfloat16 g_qh[(size_t)MROWS*HH], g_ql[(size_t)MROWS*HH];
__device__ __nv_bfloat16 g_kh[(size_t)MROWS*HH], g_kl[(size_t)MROWS*HH];
__device__ __nv_bfloat16 g_vth[(size_t)MROWS*HH], g_vtl[(size_t)MROWS*HH]; // [b][h][t]
// pre-converted inputs
__device__ __nv_bfloat16 g_xh[(size_t)MROWS*DIN], g_xl[(size_t)MROWS*DIN];
__device__ __nv_bfloat16 g_wh[3*HH*DIN], g_wl[3*HH*DIN];
// attention accumulators (fp32)
__device__ float g_O[(size_t)MROWS*HH];
__device__ float g_ell[MROWS];

// ---------------- helpers ----------------
__device__ __forceinline__ void mma_bf16(float* d, const uint32_t* a,
                                         uint32_t b0, uint32_t b1) {
    asm volatile(
        "mma.sync.aligned.m16n8k16.row.col.f32.bf16.bf16.f32 "
        "{%0,%1,%2,%3}, {%4,%5,%6,%7}, {%8,%9}, {%0,%1,%2,%3};"
        : "+f"(d[0]), "+f"(d[1]), "+f"(d[2]), "+f"(d[3])
        : "r"(a[0]), "r"(a[1]), "r"(a[2]), "r"(a[3]), "r"(b0), "r"(b1));
}

__device__ __forceinline__ void ldsm_x4(uint32_t& r0, uint32_t& r1,
                                        uint32_t& r2, uint32_t& r3, uint32_t a) {
    asm volatile("ldmatrix.sync.aligned.m8n8.x4.shared.b16 {%0,%1,%2,%3}, [%4];"
                 : "=r"(r0), "=r"(r1), "=r"(r2), "=r"(r3) : "r"(a));
}

__device__ __forceinline__ void split_pair(float x, float y,
                                           uint32_t& h, uint32_t& l) {
    __nv_bfloat162 hv = __floats2bfloat162_rn(x, y);
    float hx = __bfloat162float(hv.x);
    float hy = __bfloat162float(hv.y);
    __nv_bfloat162 lv = __floats2bfloat162_rn(x - hx, y - hy);
    h = *reinterpret_cast<uint32_t*>(&hv);
    l = *reinterpret_cast<uint32_t*>(&lv);
}

__device__ __forceinline__ uint32_t smem_u32(const void* p) {
    uint32_t a;
    asm("{ .reg .u64 t; cvta.to.shared.u64 t, %1; cvt.u32.u64 %0, t; }"
        : "=r"(a) : "l"(p));
    return a;
}

__device__ __forceinline__ void cpa16(uint32_t dst, const void* src) {
    asm volatile("cp.async.cg.shared.global [%0], [%1], 16;"
                 :: "r"(dst), "l"(src) : "memory");
}
#define CPA_COMMIT() asm volatile("cp.async.commit_group;" ::: "memory")
#define CPA_WAIT0()  asm volatile("cp.async.wait_group 0;" ::: "memory")

#define RS 144   // smem row stride bytes

// ============================================================================
// Pre-convert + zero accumulators
// ============================================================================
__global__ __launch_bounds__(256) void convert_kernel(
    const float* __restrict__ x,
    const float* __restrict__ Wq, const float* __restrict__ Wk,
    const float* __restrict__ Wv)
{
    const size_t tid0 = (size_t)blockIdx.x * 256 + threadIdx.x;
    const size_t stride = (size_t)gridDim.x * 256;
    const size_t NX = (size_t)MROWS * DIN / 4;
    for (size_t t = tid0; t < NX; t += stride) {
        float4 v = ((const float4*)x)[t];
        uint32_t h0, l0, h1, l1;
        split_pair(v.x, v.y, h0, l0);
        split_pair(v.z, v.w, h1, l1);
        ((uint2*)g_xh)[t] = make_uint2(h0, h1);
        ((uint2*)g_xl)[t] = make_uint2(l0, l1);
    }
    const size_t NW = (size_t)HH * DIN / 4;
    for (size_t t = tid0; t < 3 * NW; t += stride) {
        const int set = (int)(t / NW);
        const size_t o = t - (size_t)set * NW;
        const float* W = (set == 0) ? Wq : (set == 1) ? Wk : Wv;
        float4 v = ((const float4*)W)[o];
        uint32_t h0, l0, h1, l1;
        split_pair(v.x, v.y, h0, l0);
        split_pair(v.z, v.w, h1, l1);
        ((uint2*)g_wh)[t] = make_uint2(h0, h1);
        ((uint2*)g_wl)[t] = make_uint2(l0, l1);
    }
    const float4 z4 = make_float4(0.f, 0.f, 0.f, 0.f);
    const size_t NO = (size_t)MROWS * HH / 4;
    for (size_t t = tid0; t < NO; t += stride) ((float4*)g_O)[t] = z4;
    for (size_t t = tid0; t < MROWS / 4; t += stride) ((float4*)g_ell)[t] = z4;
}

// ============================================================================
// Projection: grid=(128,3), 256 thr, cp.async double buffer + ldmatrix.
// ============================================================================
#define P_XH 0
#define P_XL (128*RS)
#define P_WH (256*RS)
#define P_WL (256*RS + 64*RS)
#define PBUF (384*RS)
#define PROJ_SMEM (2*PBUF)

__global__ __launch_bounds__(256, 1) void proj_kernel(
    const float* __restrict__ bq, const float* __restrict__ bk,
    const float* __restrict__ bv)
{
    extern __shared__ char smp[];
    __shared__ float s_bias[64];
    const uint32_t sbase = smem_u32(smp);

    const int tid = threadIdx.x;
    const int wid = tid >> 5, lane = tid & 31;
    const int g = lane >> 2, tg = lane & 3;
    const int m0 = blockIdx.x * 128;
    const int my = blockIdx.y;

    const float* bias = (my == 0) ? bq : (my == 1) ? bk : bv;
    if (tid < 64) s_bias[tid] = bias[tid];

    const size_t wset = (size_t)my * HH * DIN;

    auto stage = [&](int kc, int bi) {
        const int k0 = kc * 64;
        const uint32_t bb = sbase + bi * PBUF;
#pragma unroll
        for (int u = tid; u < 3072; u += 256) {
            uint32_t dst; const void* src;
            if (u < 2048) {
                const int comp = u >> 10;
                const int idx = u & 1023;
                const int r = idx >> 3, c8 = idx & 7;
                const __nv_bfloat16* gsrc = comp ? g_xl : g_xh;
                src = gsrc + (size_t)(m0 + r) * DIN + k0 + c8 * 8;
                dst = bb + (comp ? P_XL : P_XH) + r * RS + c8 * 16;
            } else {
                const int comp = (u - 2048) >> 9;
                const int idx = (u - 2048) & 511;
                const int r = idx >> 3, c8 = idx & 7;
                const __nv_bfloat16* gsrc = comp ? g_wl : g_wh;
                src = gsrc + wset + (size_t)r * DIN + k0 + c8 * 8;
                dst = bb + (comp ? P_WL : P_WH) + r * RS + c8 * 16;
            }
            cpa16(dst, src);
        }
        CPA_COMMIT();
    };

    // per-lane ldmatrix offsets
    const uint32_t aoff = (lane & 7) * RS + ((lane >> 3) & 1) * 8 * RS
                        + ((lane >> 4) & 1) * 16;            // A: m16 x k16
    const uint32_t boff = (lane & 7) * RS + ((lane >> 4) & 1) * 8 * RS
                        + ((lane >> 3) & 1) * 16;            // B: 2 n-blocks x k16

    float acc[8][4];
#pragma unroll
    for (int n = 0; n < 8; ++n)
#pragma unroll
        for (int q = 0; q < 4; ++q) acc[n][q] = 0.f;

    stage(0, 0);
    for (int kc = 0; kc < 16; ++kc) {
        CPA_WAIT0();
        __syncthreads();
        if (kc < 15) stage(kc + 1, (kc + 1) & 1);

        const uint32_t bb = sbase + (kc & 1) * PBUF;
        const uint32_t Xh = bb + P_XH, Xl = bb + P_XL;
        const uint32_t Wh = bb + P_WH, Wl = bb + P_WL;
        const int ra = wid * 16;

#pragma unroll
        for (int ks = 0; ks < 4; ++ks) {
            uint32_t ah[4], al[4];
            ldsm_x4(ah[0], ah[1], ah[2], ah[3], Xh + ra * RS + ks * 32 + aoff);
            ldsm_x4(al[0], al[1], al[2], al[3], Xl + ra * RS + ks * 32 + aoff);
#pragma unroll
            for (int p = 0; p < 4; ++p) {
                uint32_t h0, h1, h2, h3, l0, l1, l2, l3;
                ldsm_x4(h0, h1, h2, h3, Wh + p * 16 * RS + ks * 32 + boff);
                ldsm_x4(l0, l1, l2, l3, Wl + p * 16 * RS + ks * 32 + boff);
                mma_bf16(acc[2*p],   ah, h0, h1);
                mma_bf16(acc[2*p],   al, h0, h1);
                mma_bf16(acc[2*p],   ah, l0, l1);
                mma_bf16(acc[2*p+1], ah, h2, h3);
                mma_bf16(acc[2*p+1], al, h2, h3);
                mma_bf16(acc[2*p+1], ah, l2, l3);
            }
        }
        __syncthreads();
    }

    // epilogue
    const int rA = m0 + wid * 16 + g;
    const int rB = rA + 8;
#pragma unroll
    for (int n = 0; n < 8; ++n) {
        const int col = 8 * n + 2 * tg;
        float v0 = acc[n][0] + s_bias[col];
        float v1 = acc[n][1] + s_bias[col + 1];
        float v2 = acc[n][2] + s_bias[col];
        float v3 = acc[n][3] + s_bias[col + 1];
        if (my < 2) {
            uint32_t h01, l01, h23, l23;
            split_pair(v0, v1, h01, l01);
            split_pair(v2, v3, h23, l23);
            __nv_bfloat16* oh = (my == 0) ? g_qh : g_kh;
            __nv_bfloat16* ol = (my == 0) ? g_ql : g_kl;
            *(uint32_t*)(oh + (size_t)rA * 64 + col) = h01;
            *(uint32_t*)(ol + (size_t)rA * 64 + col) = l01;
            *(uint32_t*)(oh + (size_t)rB * 64 + col) = h23;
            *(uint32_t*)(ol + (size_t)rB * 64 + col) = l23;
        } else {
            const int bA = rA >> 12, tA = rA & 4095;
            const int bB = rB >> 12, tB = rB & 4095;
            __nv_bfloat16 h;
            h = __float2bfloat16_rn(v0);
            g_vth[(size_t)(bA*64 + col  )*4096 + tA] = h;
            g_vtl[(size_t)(bA*64 + col  )*4096 + tA] = __float2bfloat16_rn(v0 - __bfloat162float(h));
            h = __float2bfloat16_rn(v1);
            g_vth[(size_t)(bA*64 + col+1)*4096 + tA] = h;
            g_vtl[(size_t)(bA*64 + col+1)*4096 + tA] = __float2bfloat16_rn(v1 - __bfloat162float(h));
            h = __float2bfloat16_rn(v2);
            g_vth[(size_t)(bB*64 + col  )*4096 + tB] = h;
            g_vtl[(size_t)(bB*64 + col  )*4096 + tB] = __float2bfloat16_rn(v2 - __bfloat162float(h));
            h = __float2bfloat16_rn(v3);
            g_vth[(size_t)(bB*64 + col+1)*4096 + tB] = h;
            g_vtl[(size_t)(bB*64 + col+1)*4096 + tB] = __float2bfloat16_rn(v3 - __bfloat162float(h));
        }
    }
}

// ============================================================================
// Attention, j-chunked: grid = 4 batches x 160 chunks; CTA = 128 thr (4 warps).
// Chunk = (rb, jc): j-tiles [jc*16, min(jc*16+16, rb+1)). Linear softmax:
// partial O, ell accumulated via red.global.add; divide kernel finishes.
// ============================================================================
#define CBUF (4*64*RS)
#define ATTN_SMEM (2*CBUF)

__global__ __launch_bounds__(128, 2) void attn_kernel()
{
    extern __shared__ char smp[];
    const uint32_t sbase = smem_u32(smp);
    const int tid = threadIdx.x;
    const int lw  = tid >> 5;
    const int lane = tid & 31;
    const int g  = lane >> 2, tg = lane & 3;

    const int b   = blockIdx.x & 3;
    const int cid = 159 - (blockIdx.x >> 2);
    int t;
    if (cid < 16) t = 0; else if (cid < 48) t = 1; else if (cid < 96) t = 2; else t = 3;
    const int off = cid - 8 * t * (t + 1);
    const int rb  = 16 * t + off / (t + 1);
    const int jc  = off % (t + 1);
    const int jt0 = jc * 16;
    const int jt1 = min(jt0 + 16, rb + 1);
    const int i0  = rb * 64;

    auto stage = [&](int jt, int bi) {
        const int j0 = jt * 64;
        const uint32_t bb = sbase + bi * CBUF;
#pragma unroll
        for (int i = tid; i < 2048; i += 128) {
            const int comp = i >> 9;
            const int idx = i & 511;
            const int r = idx >> 3, c8 = idx & 7;
            const void* src;
            if (comp == 0)
                src = g_qh + (size_t)(b * 4096 + j0 + r) * 64 + c8 * 8;
            else if (comp == 1)
                src = g_ql + (size_t)(b * 4096 + j0 + r) * 64 + c8 * 8;
            else if (comp == 2)
                src = g_vth + (size_t)(b * 64 + r) * 4096 + j0 + c8 * 8;
            else
                src = g_vtl + (size_t)(b * 64 + r) * 4096 + j0 + c8 * 8;
            cpa16(bb + comp * (64 * RS) + r * RS + c8 * 16, src);
        }
        CPA_COMMIT();
    };

    // persistent K fragments for this warp's 16 rows
    const int rowA = i0 + lw * 16 + g;
    uint32_t kh[4][4], kl[4][4];
    {
        const size_t r0 = (size_t)(b * 4096 + rowA) * 64;
        const uint32_t* ph0 = (const uint32_t*)(g_kh + r0);
        const uint32_t* ph1 = (const uint32_t*)(g_kh + r0 + 8 * 64);
        const uint32_t* pl0 = (const uint32_t*)(g_kl + r0);
        const uint32_t* pl1 = (const uint32_t*)(g_kl + r0 + 8 * 64);
#pragma unroll
        for (int ks = 0; ks < 4; ++ks) {
            kh[ks][0] = ph0[tg + 8*ks];     kh[ks][1] = ph1[tg + 8*ks];
            kh[ks][2] = ph0[tg + 8*ks + 4]; kh[ks][3] = ph1[tg + 8*ks + 4];
            kl[ks][0] = pl0[tg + 8*ks];     kl[ks][1] = pl1[tg + 8*ks];
            kl[ks][2] = pl0[tg + 8*ks + 4]; kl[ks][3] = pl1[tg + 8*ks + 4];
        }
    }

    const uint32_t boff = (lane & 7) * RS + ((lane >> 4) & 1) * 8 * RS
                        + ((lane >> 3) & 1) * 16;

    float o[8][4];
#pragma unroll
    for (int n = 0; n < 8; ++n)
#pragma unroll
        for (int q = 0; q < 4; ++q) o[n][q] = 0.f;
    float ellA = 0.f, ellB = 0.f;

    stage(jt0, jt0 & 1);
    for (int jt = jt0; jt < jt1; ++jt) {
        const int j0 = jt * 64;
        CPA_WAIT0();
        __syncthreads();
        if (jt + 1 < jt1) stage(jt + 1, (jt + 1) & 1);

        const uint32_t bb = sbase + (jt & 1) * CBUF;
        const uint32_t Qh = bb, Ql = bb + 64 * RS;
        const uint32_t Vh = bb + 128 * RS, Vl = bb + 192 * RS;

        // ---- S = K . Q^T ----
        float s[8][4];
#pragma unroll
        for (int n = 0; n < 8; ++n)
#pragma unroll
            for (int q = 0; q < 4; ++q) s[n][q] = 0.f;

#pragma unroll
        for (int ks = 0; ks < 4; ++ks) {
#pragma unroll
            for (int p = 0; p < 4; ++p) {
                uint32_t h0, h1, h2, h3, l0, l1, l2, l3;
                ldsm_x4(h0, h1, h2, h3, Qh + p * 16 * RS + ks * 32 + boff);
                ldsm_x4(l0, l1, l2, l3, Ql + p * 16 * RS + ks * 32 + boff);
                mma_bf16(s[2*p],   kh[ks], h0, h1);
                mma_bf16(s[2*p],   kl[ks], h0, h1);
                mma_bf16(s[2*p],   kh[ks], l0, l1);
                mma_bf16(s[2*p+1], kh[ks], h2, h3);
                mma_bf16(s[2*p+1], kl[ks], h2, h3);
                mma_bf16(s[2*p+1], kh[ks], l2, l3);
            }
        }

        // ---- P = exp(S), mask, ell, pack ----
        uint32_t pha[4][4], pla[4][4];
        const bool diag = (jt == rb);
#pragma unroll
        for (int n = 0; n < 8; ++n) {
            float p0 = __expf(s[n][0]);
            float p1 = __expf(s[n][1]);
            float p2 = __expf(s[n][2]);
            float p3 = __expf(s[n][3]);
            if (diag) {
                const int col = j0 + 8 * n + 2 * tg;
                if (col     > rowA)     p0 = 0.f;
                if (col + 1 > rowA)     p1 = 0.f;
                if (col     > rowA + 8) p2 = 0.f;
                if (col + 1 > rowA + 8) p3 = 0.f;
            }
            ellA += p0 + p1;
            ellB += p2 + p3;
            uint32_t h01, l01, h23, l23;
            split_pair(p0, p1, h01, l01);
            split_pair(p2, p3, h23, l23);
            const int tt = n >> 1;
            if ((n & 1) == 0) {
                pha[tt][0] = h01; pha[tt][1] = h23;
                pla[tt][0] = l01; pla[tt][1] = l23;
            } else {
                pha[tt][2] = h01; pha[tt][3] = h23;
                pla[tt][2] = l01; pla[tt][3] = l23;
            }
        }

        // ---- O += P . V ----
#pragma unroll
        for (int kt = 0; kt < 4; ++kt) {
#pragma unroll
            for (int p = 0; p < 4; ++p) {
                uint32_t h0, h1, h2, h3, l0, l1, l2, l3;
                ldsm_x4(h0, h1, h2, h3, Vh + p * 16 * RS + kt * 32 + boff);
                ldsm_x4(l0, l1, l2, l3, Vl + p * 16 * RS + kt * 32 + boff);
                mma_bf16(o[2*p],   pha[kt], h0, h1);
                mma_bf16(o[2*p],   pla[kt], h0, h1);
                mma_bf16(o[2*p],   pha[kt], l0, l1);
                mma_bf16(o[2*p+1], pha[kt], h2, h3);
                mma_bf16(o[2*p+1], pla[kt], h2, h3);
                mma_bf16(o[2*p+1], pha[kt], l2, l3);
            }
        }
    }

    // ---- epilogue: atomic accumulate O, ell ----
    ellA += __shfl_xor_sync(0xffffffffu, ellA, 1);
    ellA += __shfl_xor_sync(0xffffffffu, ellA, 2);
    ellB += __shfl_xor_sync(0xffffffffu, ellB, 1);
    ellB += __shfl_xor_sync(0xffffffffu, ellB, 2);
    if (tg == 0) {
        atomicAdd(&g_ell[b * 4096 + rowA],     ellA);
        atomicAdd(&g_ell[b * 4096 + rowA + 8], ellB);
    }
    float* OA = g_O + (size_t)(b * 4096 + rowA) * 64;
    float* OB = OA + 8 * 64;
#pragma unroll
    for (int n = 0; n < 8; ++n) {
        const int col = 8 * n + 2 * tg;
        atomicAdd(OA + col,     o[n][0]);
        atomicAdd(OA + col + 1, o[n][1]);
        atomicAdd(OB + col,     o[n][2]);
        atomicAdd(OB + col + 1, o[n][3]);
    }
}

// ============================================================================
// Divide: out = O / ell
// ============================================================================
__global__ __launch_bounds__(256) void divide_kernel(float* __restrict__ out)
{
    const size_t tid0 = (size_t)blockIdx.x * 256 + threadIdx.x;
    const size_t stride = (size_t)gridDim.x * 256;
    const size_t N = (size_t)MROWS * HH / 4;   // float4 units, 16 per row
    for (size_t u = tid0; u < N; u += stride) {
        const size_t m = u >> 4;
        const float inv = 1.0f / g_ell[m];
        float4 v = ((const float4*)g_O)[u];
        v.x *= inv; v.y *= inv; v.z *= inv; v.w *= inv;
        ((float4*)out)[u] = v;
    }
}

// ============================================================================
extern "C" void kernel_launch(void* const* d_in, const int* in_sizes, int n_in,
                              void* d_out, int out_size)
{
    const float* x  = (const float*)d_in[0];
    const float* Wq = (const float*)d_in[1];
    const float* bq = (const float*)d_in[2];
    const float* Wk = (const float*)d_in[3];
    const float* bk = (const float*)d_in[4];
    const float* Wv = (const float*)d_in[5];
    const float* bv = (const float*)d_in[6];
    float* out = (float*)d_out;

    cudaFuncSetAttribute(proj_kernel, cudaFuncAttributeMaxDynamicSharedMemorySize, PROJ_SMEM);
    cudaFuncSetAttribute(attn_kernel, cudaFuncAttributeMaxDynamicSharedMemorySize, ATTN_SMEM);

    convert_kernel<<<1024, 256>>>(x, Wq, Wk, Wv);
    proj_kernel<<<dim3(128, 3), 256, PROJ_SMEM>>>(bq, bk, bv);
    attn_kernel<<<4 * 160, 128, ATTN_SMEM>>>();
    divide_kernel<<<512, 256>>>(out);
}

// round 7
// speedup vs baseline: 4.4732x; 1.0481x over previous
#include <cuda_runtime.h>
#include <cuda_bf16.h>
#include <cstdint>

#define BB 4
#define TT 4096
#define DIN 1024
#define HH 64
#define MROWS (BB*TT)

// bf16 hi/lo split scratch
__device__ __nv_bfloat16 g_qh[(size_t)MROWS*HH], g_ql[(size_t)MROWS*HH];
__device__ __nv_bfloat16 g_kh[(size_t)MROWS*HH], g_kl[(size_t)MROWS*HH];
__device__ __nv_bfloat16 g_vth[(size_t)MROWS*HH], g_vtl[(size_t)MROWS*HH]; // [b][h][t]
// pre-converted inputs
__device__ __nv_bfloat16 g_xh[(size_t)MROWS*DIN], g_xl[(size_t)MROWS*DIN];
__device__ __nv_bfloat16 g_wh[3*HH*DIN], g_wl[3*HH*DIN];
// attention accumulators (fp32)
__device__ float g_O[(size_t)MROWS*HH];
__device__ float g_ell[MROWS];

// ---------------- helpers ----------------
__device__ __forceinline__ void mma_bf16(float* d, const uint32_t* a,
                                         uint32_t b0, uint32_t b1) {
    asm volatile(
        "mma.sync.aligned.m16n8k16.row.col.f32.bf16.bf16.f32 "
        "{%0,%1,%2,%3}, {%4,%5,%6,%7}, {%8,%9}, {%0,%1,%2,%3};"
        : "+f"(d[0]), "+f"(d[1]), "+f"(d[2]), "+f"(d[3])
        : "r"(a[0]), "r"(a[1]), "r"(a[2]), "r"(a[3]), "r"(b0), "r"(b1));
}

__device__ __forceinline__ void ldsm_x4(uint32_t& r0, uint32_t& r1,
                                        uint32_t& r2, uint32_t& r3, uint32_t a) {
    asm volatile("ldmatrix.sync.aligned.m8n8.x4.shared.b16 {%0,%1,%2,%3}, [%4];"
                 : "=r"(r0), "=r"(r1), "=r"(r2), "=r"(r3) : "r"(a));
}

__device__ __forceinline__ void split_pair(float x, float y,
                                           uint32_t& h, uint32_t& l) {
    __nv_bfloat162 hv = __floats2bfloat162_rn(x, y);
    float hx = __bfloat162float(hv.x);
    float hy = __bfloat162float(hv.y);
    __nv_bfloat162 lv = __floats2bfloat162_rn(x - hx, y - hy);
    h = *reinterpret_cast<uint32_t*>(&hv);
    l = *reinterpret_cast<uint32_t*>(&lv);
}

__device__ __forceinline__ uint32_t smem_u32(const void* p) {
    uint32_t a;
    asm("{ .reg .u64 t; cvta.to.shared.u64 t, %1; cvt.u32.u64 %0, t; }"
        : "=r"(a) : "l"(p));
    return a;
}

__device__ __forceinline__ void cpa16(uint32_t dst, const void* src) {
    asm volatile("cp.async.cg.shared.global [%0], [%1], 16;"
                 :: "r"(dst), "l"(src) : "memory");
}
#define CPA_COMMIT() asm volatile("cp.async.commit_group;" ::: "memory")
#define CPA_WAIT0()  asm volatile("cp.async.wait_group 0;" ::: "memory")

__device__ __forceinline__ void redg_v2(float* p, float a, float b) {
    asm volatile("red.global.add.v2.f32 [%0], {%1, %2};"
                 :: "l"(p), "f"(a), "f"(b) : "memory");
}

#define RS 144   // smem row stride bytes

// ============================================================================
// Pre-convert + zero accumulators
// ============================================================================
__global__ __launch_bounds__(256) void convert_kernel(
    const float* __restrict__ x,
    const float* __restrict__ Wq, const float* __restrict__ Wk,
    const float* __restrict__ Wv)
{
    const size_t tid0 = (size_t)blockIdx.x * 256 + threadIdx.x;
    const size_t stride = (size_t)gridDim.x * 256;
    const size_t NX = (size_t)MROWS * DIN / 4;
    for (size_t t = tid0; t < NX; t += stride) {
        float4 v = ((const float4*)x)[t];
        uint32_t h0, l0, h1, l1;
        split_pair(v.x, v.y, h0, l0);
        split_pair(v.z, v.w, h1, l1);
        ((uint2*)g_xh)[t] = make_uint2(h0, h1);
        ((uint2*)g_xl)[t] = make_uint2(l0, l1);
    }
    const size_t NW = (size_t)HH * DIN / 4;
    for (size_t t = tid0; t < 3 * NW; t += stride) {
        const int set = (int)(t / NW);
        const size_t o = t - (size_t)set * NW;
        const float* W = (set == 0) ? Wq : (set == 1) ? Wk : Wv;
        float4 v = ((const float4*)W)[o];
        uint32_t h0, l0, h1, l1;
        split_pair(v.x, v.y, h0, l0);
        split_pair(v.z, v.w, h1, l1);
        ((uint2*)g_wh)[t] = make_uint2(h0, h1);
        ((uint2*)g_wl)[t] = make_uint2(l0, l1);
    }
    const float4 z4 = make_float4(0.f, 0.f, 0.f, 0.f);
    const size_t NO = (size_t)MROWS * HH / 4;
    for (size_t t = tid0; t < NO; t += stride) ((float4*)g_O)[t] = z4;
    for (size_t t = tid0; t < MROWS / 4; t += stride) ((float4*)g_ell)[t] = z4;
}

// ============================================================================
// Projection: grid=(128,3), 256 thr, 2 CTAs/SM, cp.async double buffer + ldsm.
// ============================================================================
#define P_XH 0
#define P_XL (128*RS)
#define P_WH (256*RS)
#define P_WL (256*RS + 64*RS)
#define PBUF (384*RS)
#define PROJ_SMEM (2*PBUF)

__global__ __launch_bounds__(256, 2) void proj_kernel(
    const float* __restrict__ bq, const float* __restrict__ bk,
    const float* __restrict__ bv)
{
    extern __shared__ char smp[];
    __shared__ float s_bias[64];
    const uint32_t sbase = smem_u32(smp);

    const int tid = threadIdx.x;
    const int wid = tid >> 5, lane = tid & 31;
    const int g = lane >> 2, tg = lane & 3;
    const int m0 = blockIdx.x * 128;
    const int my = blockIdx.y;

    const float* bias = (my == 0) ? bq : (my == 1) ? bk : bv;
    if (tid < 64) s_bias[tid] = bias[tid];

    const size_t wset = (size_t)my * HH * DIN;

    auto stage = [&](int kc, int bi) {
        const int k0 = kc * 64;
        const uint32_t bb = sbase + bi * PBUF;
#pragma unroll
        for (int u = tid; u < 3072; u += 256) {
            uint32_t dst; const void* src;
            if (u < 2048) {
                const int comp = u >> 10;
                const int idx = u & 1023;
                const int r = idx >> 3, c8 = idx & 7;
                const __nv_bfloat16* gsrc = comp ? g_xl : g_xh;
                src = gsrc + (size_t)(m0 + r) * DIN + k0 + c8 * 8;
                dst = bb + (comp ? P_XL : P_XH) + r * RS + c8 * 16;
            } else {
                const int comp = (u - 2048) >> 9;
                const int idx = (u - 2048) & 511;
                const int r = idx >> 3, c8 = idx & 7;
                const __nv_bfloat16* gsrc = comp ? g_wl : g_wh;
                src = gsrc + wset + (size_t)r * DIN + k0 + c8 * 8;
                dst = bb + (comp ? P_WL : P_WH) + r * RS + c8 * 16;
            }
            cpa16(dst, src);
        }
        CPA_COMMIT();
    };

    const uint32_t aoff = (lane & 7) * RS + ((lane >> 3) & 1) * 8 * RS
                        + ((lane >> 4) & 1) * 16;
    const uint32_t boff = (lane & 7) * RS + ((lane >> 4) & 1) * 8 * RS
                        + ((lane >> 3) & 1) * 16;

    float acc[8][4];
#pragma unroll
    for (int n = 0; n < 8; ++n)
#pragma unroll
        for (int q = 0; q < 4; ++q) acc[n][q] = 0.f;

    stage(0, 0);
    for (int kc = 0; kc < 16; ++kc) {
        CPA_WAIT0();
        __syncthreads();
        if (kc < 15) stage(kc + 1, (kc + 1) & 1);

        const uint32_t bb = sbase + (kc & 1) * PBUF;
        const uint32_t Xh = bb + P_XH, Xl = bb + P_XL;
        const uint32_t Wh = bb + P_WH, Wl = bb + P_WL;
        const int ra = wid * 16;

#pragma unroll
        for (int ks = 0; ks < 4; ++ks) {
            uint32_t ah[4], al[4];
            ldsm_x4(ah[0], ah[1], ah[2], ah[3], Xh + ra * RS + ks * 32 + aoff);
            ldsm_x4(al[0], al[1], al[2], al[3], Xl + ra * RS + ks * 32 + aoff);
#pragma unroll
            for (int p = 0; p < 4; ++p) {
                uint32_t h0, h1, h2, h3, l0, l1, l2, l3;
                ldsm_x4(h0, h1, h2, h3, Wh + p * 16 * RS + ks * 32 + boff);
                ldsm_x4(l0, l1, l2, l3, Wl + p * 16 * RS + ks * 32 + boff);
                mma_bf16(acc[2*p],   ah, h0, h1);
                mma_bf16(acc[2*p],   al, h0, h1);
                mma_bf16(acc[2*p],   ah, l0, l1);
                mma_bf16(acc[2*p+1], ah, h2, h3);
                mma_bf16(acc[2*p+1], al, h2, h3);
                mma_bf16(acc[2*p+1], ah, l2, l3);
            }
        }
        __syncthreads();
    }

    // epilogue
    const int rA = m0 + wid * 16 + g;
    const int rB = rA + 8;
#pragma unroll
    for (int n = 0; n < 8; ++n) {
        const int col = 8 * n + 2 * tg;
        float v0 = acc[n][0] + s_bias[col];
        float v1 = acc[n][1] + s_bias[col + 1];
        float v2 = acc[n][2] + s_bias[col];
        float v3 = acc[n][3] + s_bias[col + 1];
        if (my < 2) {
            uint32_t h01, l01, h23, l23;
            split_pair(v0, v1, h01, l01);
            split_pair(v2, v3, h23, l23);
            __nv_bfloat16* oh = (my == 0) ? g_qh : g_kh;
            __nv_bfloat16* ol = (my == 0) ? g_ql : g_kl;
            *(uint32_t*)(oh + (size_t)rA * 64 + col) = h01;
            *(uint32_t*)(ol + (size_t)rA * 64 + col) = l01;
            *(uint32_t*)(oh + (size_t)rB * 64 + col) = h23;
            *(uint32_t*)(ol + (size_t)rB * 64 + col) = l23;
        } else {
            const int bA = rA >> 12, tA = rA & 4095;
            const int bB = rB >> 12, tB = rB & 4095;
            __nv_bfloat16 h;
            h = __float2bfloat16_rn(v0);
            g_vth[(size_t)(bA*64 + col  )*4096 + tA] = h;
            g_vtl[(size_t)(bA*64 + col  )*4096 + tA] = __float2bfloat16_rn(v0 - __bfloat162float(h));
            h = __float2bfloat16_rn(v1);
            g_vth[(size_t)(bA*64 + col+1)*4096 + tA] = h;
            g_vtl[(size_t)(bA*64 + col+1)*4096 + tA] = __float2bfloat16_rn(v1 - __bfloat162float(h));
            h = __float2bfloat16_rn(v2);
            g_vth[(size_t)(bB*64 + col  )*4096 + tB] = h;
            g_vtl[(size_t)(bB*64 + col  )*4096 + tB] = __float2bfloat16_rn(v2 - __bfloat162float(h));
            h = __float2bfloat16_rn(v3);
            g_vth[(size_t)(bB*64 + col+1)*4096 + tB] = h;
            g_vtl[(size_t)(bB*64 + col+1)*4096 + tB] = __float2bfloat16_rn(v3 - __bfloat162float(h));
        }
    }
}

// ============================================================================
// Attention, chunk = 8 j-tiles: grid = 4 x 288; CTA = 128 thr, 3 CTAs/SM.
// K tile lives in SMEM (A-fragments via ldmatrix); single QV buffer.
// Partial (O, ell) accumulated with red.global.add; divide kernel finishes.
// ============================================================================
#define K_REG   (2*64*RS)               // 18432: Kh, Kl
#define QV_BUF  (4*64*RS)               // 36864: Qh, Ql, Vh, Vl
#define ATTN_SMEM (K_REG + QV_BUF)      // 55296

__global__ __launch_bounds__(128, 3) void attn_kernel()
{
    extern __shared__ char smp[];
    const uint32_t sbase = smem_u32(smp);
    const int tid = threadIdx.x;
    const int lw  = tid >> 5;
    const int lane = tid & 31;
    const int g  = lane >> 2, tg = lane & 3;

    const int b   = blockIdx.x & 3;
    const int cid = 287 - (blockIdx.x >> 2);
    const int t = (cid >= 224) ? 7 : (cid >= 168) ? 6 : (cid >= 120) ? 5 :
                  (cid >= 80)  ? 4 : (cid >= 48)  ? 3 : (cid >= 24)  ? 2 :
                  (cid >= 8)   ? 1 : 0;
    const int off = cid - 4 * t * (t + 1);
    const int rb  = 8 * t + off / (t + 1);
    const int jc  = off % (t + 1);
    const int jt0 = jc * 8;
    const int jt1 = min(jt0 + 8, rb + 1);
    const int i0  = rb * 64;

    const uint32_t Kb = sbase;            // Kh at 0, Kl at +64*RS
    const uint32_t Qb = sbase + K_REG;    // Qh, Ql, Vh, Vl

    // stage K tile (own commit group)
#pragma unroll
    for (int i = tid; i < 1024; i += 128) {
        const int comp = i >> 9;
        const int idx = i & 511;
        const int r = idx >> 3, c8 = idx & 7;
        const __nv_bfloat16* gsrc = comp ? g_kl : g_kh;
        cpa16(Kb + comp * (64 * RS) + r * RS + c8 * 16,
              gsrc + (size_t)(b * 4096 + i0 + r) * 64 + c8 * 8);
    }
    CPA_COMMIT();

    auto stage = [&](int jt) {
        const int j0 = jt * 64;
#pragma unroll
        for (int i = tid; i < 2048; i += 128) {
            const int comp = i >> 9;
            const int idx = i & 511;
            const int r = idx >> 3, c8 = idx & 7;
            const void* src;
            if (comp == 0)
                src = g_qh + (size_t)(b * 4096 + j0 + r) * 64 + c8 * 8;
            else if (comp == 1)
                src = g_ql + (size_t)(b * 4096 + j0 + r) * 64 + c8 * 8;
            else if (comp == 2)
                src = g_vth + (size_t)(b * 64 + r) * 4096 + j0 + c8 * 8;
            else
                src = g_vtl + (size_t)(b * 64 + r) * 4096 + j0 + c8 * 8;
            cpa16(Qb + comp * (64 * RS) + r * RS + c8 * 16, src);
        }
        CPA_COMMIT();
    };

    const uint32_t aoff = (lane & 7) * RS + ((lane >> 3) & 1) * 8 * RS
                        + ((lane >> 4) & 1) * 16;
    const uint32_t boff = (lane & 7) * RS + ((lane >> 4) & 1) * 8 * RS
                        + ((lane >> 3) & 1) * 16;
    const int rowA = i0 + lw * 16 + g;

    float o[8][4];
#pragma unroll
    for (int n = 0; n < 8; ++n)
#pragma unroll
        for (int q = 0; q < 4; ++q) o[n][q] = 0.f;
    float ellA = 0.f, ellB = 0.f;

    for (int jt = jt0; jt < jt1; ++jt) {
        const int j0 = jt * 64;
        stage(jt);
        CPA_WAIT0();
        __syncthreads();

        const uint32_t Qh = Qb, Ql = Qb + 64 * RS;
        const uint32_t Vh = Qb + 128 * RS, Vl = Qb + 192 * RS;

        // ---- S = K . Q^T ----
        float s[8][4];
#pragma unroll
        for (int n = 0; n < 8; ++n)
#pragma unroll
            for (int q = 0; q < 4; ++q) s[n][q] = 0.f;

#pragma unroll
        for (int ks = 0; ks < 4; ++ks) {
            uint32_t kh[4], kl[4];
            ldsm_x4(kh[0], kh[1], kh[2], kh[3],
                    Kb + (lw * 16) * RS + ks * 32 + aoff);
            ldsm_x4(kl[0], kl[1], kl[2], kl[3],
                    Kb + 64 * RS + (lw * 16) * RS + ks * 32 + aoff);
#pragma unroll
            for (int p = 0; p < 4; ++p) {
                uint32_t h0, h1, h2, h3, l0, l1, l2, l3;
                ldsm_x4(h0, h1, h2, h3, Qh + p * 16 * RS + ks * 32 + boff);
                ldsm_x4(l0, l1, l2, l3, Ql + p * 16 * RS + ks * 32 + boff);
                mma_bf16(s[2*p],   kh, h0, h1);
                mma_bf16(s[2*p],   kl, h0, h1);
                mma_bf16(s[2*p],   kh, l0, l1);
                mma_bf16(s[2*p+1], kh, h2, h3);
                mma_bf16(s[2*p+1], kl, h2, h3);
                mma_bf16(s[2*p+1], kh, l2, l3);
            }
        }

        // ---- P = exp(S), mask, ell, pack ----
        uint32_t pha[4][4], pla[4][4];
        const bool diag = (jt == rb);
#pragma unroll
        for (int n = 0; n < 8; ++n) {
            float p0 = __expf(s[n][0]);
            float p1 = __expf(s[n][1]);
            float p2 = __expf(s[n][2]);
            float p3 = __expf(s[n][3]);
            if (diag) {
                const int col = j0 + 8 * n + 2 * tg;
                if (col     > rowA)     p0 = 0.f;
                if (col + 1 > rowA)     p1 = 0.f;
                if (col     > rowA + 8) p2 = 0.f;
                if (col + 1 > rowA + 8) p3 = 0.f;
            }
            ellA += p0 + p1;
            ellB += p2 + p3;
            uint32_t h01, l01, h23, l23;
            split_pair(p0, p1, h01, l01);
            split_pair(p2, p3, h23, l23);
            const int tt = n >> 1;
            if ((n & 1) == 0) {
                pha[tt][0] = h01; pha[tt][1] = h23;
                pla[tt][0] = l01; pla[tt][1] = l23;
            } else {
                pha[tt][2] = h01; pha[tt][3] = h23;
                pla[tt][2] = l01; pla[tt][3] = l23;
            }
        }

        // ---- O += P . V ----
#pragma unroll
        for (int kt = 0; kt < 4; ++kt) {
#pragma unroll
            for (int p = 0; p < 4; ++p) {
                uint32_t h0, h1, h2, h3, l0, l1, l2, l3;
                ldsm_x4(h0, h1, h2, h3, Vh + p * 16 * RS + kt * 32 + boff);
                ldsm_x4(l0, l1, l2, l3, Vl + p * 16 * RS + kt * 32 + boff);
                mma_bf16(o[2*p],   pha[kt], h0, h1);
                mma_bf16(o[2*p],   pla[kt], h0, h1);
                mma_bf16(o[2*p],   pha[kt], l0, l1);
                mma_bf16(o[2*p+1], pha[kt], h2, h3);
                mma_bf16(o[2*p+1], pla[kt], h2, h3);
                mma_bf16(o[2*p+1], pha[kt], l2, l3);
            }
        }
        __syncthreads();   // all reads of QV buffer done before next stage
    }

    // ---- epilogue: vector red accumulate O, scalar ell ----
    ellA += __shfl_xor_sync(0xffffffffu, ellA, 1);
    ellA += __shfl_xor_sync(0xffffffffu, ellA, 2);
    ellB += __shfl_xor_sync(0xffffffffu, ellB, 1);
    ellB += __shfl_xor_sync(0xffffffffu, ellB, 2);
    if (tg == 0) {
        atomicAdd(&g_ell[b * 4096 + rowA],     ellA);
        atomicAdd(&g_ell[b * 4096 + rowA + 8], ellB);
    }
    float* OA = g_O + (size_t)(b * 4096 + rowA) * 64;
    float* OB = OA + 8 * 64;
#pragma unroll
    for (int n = 0; n < 8; ++n) {
        const int col = 8 * n + 2 * tg;
        redg_v2(OA + col, o[n][0], o[n][1]);
        redg_v2(OB + col, o[n][2], o[n][3]);
    }
}

// ============================================================================
// Divide: out = O / ell
// ============================================================================
__global__ __launch_bounds__(256) void divide_kernel(float* __restrict__ out)
{
    const size_t tid0 = (size_t)blockIdx.x * 256 + threadIdx.x;
    const size_t stride = (size_t)gridDim.x * 256;
    const size_t N = (size_t)MROWS * HH / 4;
    for (size_t u = tid0; u < N; u += stride) {
        const size_t m = u >> 4;
        const float inv = 1.0f / g_ell[m];
        float4 v = ((const float4*)g_O)[u];
        v.x *= inv; v.y *= inv; v.z *= inv; v.w *= inv;
        ((float4*)out)[u] = v;
    }
}

// ============================================================================
extern "C" void kernel_launch(void* const* d_in, const int* in_sizes, int n_in,
                              void* d_out, int out_size)
{
    const float* x  = (const float*)d_in[0];
    const float* Wq = (const float*)d_in[1];
    const float* bq = (const float*)d_in[2];
    const float* Wk = (const float*)d_in[3];
    const float* bk = (const float*)d_in[4];
    const float* Wv = (const float*)d_in[5];
    const float* bv = (const float*)d_in[6];
    float* out = (float*)d_out;

    cudaFuncSetAttribute(proj_kernel, cudaFuncAttributeMaxDynamicSharedMemorySize, PROJ_SMEM);
    cudaFuncSetAttribute(attn_kernel, cudaFuncAttributeMaxDynamicSharedMemorySize, ATTN_SMEM);

    convert_kernel<<<1024, 256>>>(x, Wq, Wk, Wv);
    proj_kernel<<<dim3(128, 3), 256, PROJ_SMEM>>>(bq, bk, bv);
    attn_kernel<<<4 * 288, 128, ATTN_SMEM>>>();
    divide_kernel<<<1024, 256>>>(out);
}

// round 8
// speedup vs baseline: 4.5059x; 1.0073x over previous
#include <cuda_runtime.h>
#include <cuda_bf16.h>
#include <cstdint>

#define BB 4
#define TT 4096
#define DIN 1024
#define HH 64
#define MROWS (BB*TT)

// bf16 hi/lo split scratch
__device__ __nv_bfloat16 g_qh[(size_t)MROWS*HH], g_ql[(size_t)MROWS*HH];
__device__ __nv_bfloat16 g_kh[(size_t)MROWS*HH], g_kl[(size_t)MROWS*HH];
__device__ __nv_bfloat16 g_vth[(size_t)MROWS*HH], g_vtl[(size_t)MROWS*HH]; // [b][h][t]
// pre-converted inputs
__device__ __nv_bfloat16 g_xh[(size_t)MROWS*DIN], g_xl[(size_t)MROWS*DIN];
__device__ __nv_bfloat16 g_wh[3*HH*DIN], g_wl[3*HH*DIN];
// attention accumulators (fp32)
__device__ float g_O[(size_t)MROWS*HH];
__device__ float g_ell[MROWS];

// ---------------- helpers ----------------
__device__ __forceinline__ void mma_bf16(float* d, const uint32_t* a,
                                         uint32_t b0, uint32_t b1) {
    asm volatile(
        "mma.sync.aligned.m16n8k16.row.col.f32.bf16.bf16.f32 "
        "{%0,%1,%2,%3}, {%4,%5,%6,%7}, {%8,%9}, {%0,%1,%2,%3};"
        : "+f"(d[0]), "+f"(d[1]), "+f"(d[2]), "+f"(d[3])
        : "r"(a[0]), "r"(a[1]), "r"(a[2]), "r"(a[3]), "r"(b0), "r"(b1));
}

__device__ __forceinline__ void ldsm_x4(uint32_t& r0, uint32_t& r1,
                                        uint32_t& r2, uint32_t& r3, uint32_t a) {
    asm volatile("ldmatrix.sync.aligned.m8n8.x4.shared.b16 {%0,%1,%2,%3}, [%4];"
                 : "=r"(r0), "=r"(r1), "=r"(r2), "=r"(r3) : "r"(a));
}

__device__ __forceinline__ void split_pair(float x, float y,
                                           uint32_t& h, uint32_t& l) {
    __nv_bfloat162 hv = __floats2bfloat162_rn(x, y);
    float hx = __bfloat162float(hv.x);
    float hy = __bfloat162float(hv.y);
    __nv_bfloat162 lv = __floats2bfloat162_rn(x - hx, y - hy);
    h = *reinterpret_cast<uint32_t*>(&hv);
    l = *reinterpret_cast<uint32_t*>(&lv);
}

__device__ __forceinline__ uint32_t smem_u32(const void* p) {
    uint32_t a;
    asm("{ .reg .u64 t; cvta.to.shared.u64 t, %1; cvt.u32.u64 %0, t; }"
        : "=r"(a) : "l"(p));
    return a;
}

__device__ __forceinline__ void cpa16(uint32_t dst, const void* src) {
    asm volatile("cp.async.cg.shared.global [%0], [%1], 16;"
                 :: "r"(dst), "l"(src) : "memory");
}
#define CPA_COMMIT() asm volatile("cp.async.commit_group;" ::: "memory")
#define CPA_WAIT(N)  asm volatile("cp.async.wait_group %0;" :: "n"(N) : "memory")

__device__ __forceinline__ void redg_v2(float* p, float a, float b) {
    asm volatile("red.global.add.v2.f32 [%0], {%1, %2};"
                 :: "l"(p), "f"(a), "f"(b) : "memory");
}

#define RS 144   // smem row stride bytes

// ============================================================================
// Pre-convert + zero accumulators
// ============================================================================
__global__ __launch_bounds__(256) void convert_kernel(
    const float* __restrict__ x,
    const float* __restrict__ Wq, const float* __restrict__ Wk,
    const float* __restrict__ Wv)
{
    const size_t tid0 = (size_t)blockIdx.x * 256 + threadIdx.x;
    const size_t stride = (size_t)gridDim.x * 256;
    const size_t NX = (size_t)MROWS * DIN / 4;
    for (size_t t = tid0; t < NX; t += stride) {
        float4 v = ((const float4*)x)[t];
        uint32_t h0, l0, h1, l1;
        split_pair(v.x, v.y, h0, l0);
        split_pair(v.z, v.w, h1, l1);
        ((uint2*)g_xh)[t] = make_uint2(h0, h1);
        ((uint2*)g_xl)[t] = make_uint2(l0, l1);
    }
    const size_t NW = (size_t)HH * DIN / 4;
    for (size_t t = tid0; t < 3 * NW; t += stride) {
        const int set = (int)(t / NW);
        const size_t o = t - (size_t)set * NW;
        const float* W = (set == 0) ? Wq : (set == 1) ? Wk : Wv;
        float4 v = ((const float4*)W)[o];
        uint32_t h0, l0, h1, l1;
        split_pair(v.x, v.y, h0, l0);
        split_pair(v.z, v.w, h1, l1);
        ((uint2*)g_wh)[t] = make_uint2(h0, h1);
        ((uint2*)g_wl)[t] = make_uint2(l0, l1);
    }
    const float4 z4 = make_float4(0.f, 0.f, 0.f, 0.f);
    const size_t NO = (size_t)MROWS * HH / 4;
    for (size_t t = tid0; t < NO; t += stride) ((float4*)g_O)[t] = z4;
    for (size_t t = tid0; t < MROWS / 4; t += stride) ((float4*)g_ell)[t] = z4;
}

// ============================================================================
// Projection: grid=(128,3), 256 thr, 2 CTAs/SM, cp.async double buffer + ldsm.
// ============================================================================
#define P_XH 0
#define P_XL (128*RS)
#define P_WH (256*RS)
#define P_WL (256*RS + 64*RS)
#define PBUF (384*RS)
#define PROJ_SMEM (2*PBUF)

__global__ __launch_bounds__(256, 2) void proj_kernel(
    const float* __restrict__ bq, const float* __restrict__ bk,
    const float* __restrict__ bv)
{
    extern __shared__ char smp[];
    __shared__ float s_bias[64];
    const uint32_t sbase = smem_u32(smp);

    const int tid = threadIdx.x;
    const int wid = tid >> 5, lane = tid & 31;
    const int g = lane >> 2, tg = lane & 3;
    const int m0 = blockIdx.x * 128;
    const int my = blockIdx.y;

    const float* bias = (my == 0) ? bq : (my == 1) ? bk : bv;
    if (tid < 64) s_bias[tid] = bias[tid];

    const size_t wset = (size_t)my * HH * DIN;

    auto stage = [&](int kc, int bi) {
        const int k0 = kc * 64;
        const uint32_t bb = sbase + bi * PBUF;
#pragma unroll
        for (int u = tid; u < 3072; u += 256) {
            uint32_t dst; const void* src;
            if (u < 2048) {
                const int comp = u >> 10;
                const int idx = u & 1023;
                const int r = idx >> 3, c8 = idx & 7;
                const __nv_bfloat16* gsrc = comp ? g_xl : g_xh;
                src = gsrc + (size_t)(m0 + r) * DIN + k0 + c8 * 8;
                dst = bb + (comp ? P_XL : P_XH) + r * RS + c8 * 16;
            } else {
                const int comp = (u - 2048) >> 9;
                const int idx = (u - 2048) & 511;
                const int r = idx >> 3, c8 = idx & 7;
                const __nv_bfloat16* gsrc = comp ? g_wl : g_wh;
                src = gsrc + wset + (size_t)r * DIN + k0 + c8 * 8;
                dst = bb + (comp ? P_WL : P_WH) + r * RS + c8 * 16;
            }
            cpa16(dst, src);
        }
        CPA_COMMIT();
    };

    const uint32_t aoff = (lane & 7) * RS + ((lane >> 3) & 1) * 8 * RS
                        + ((lane >> 4) & 1) * 16;
    const uint32_t boff = (lane & 7) * RS + ((lane >> 4) & 1) * 8 * RS
                        + ((lane >> 3) & 1) * 16;

    float acc[8][4];
#pragma unroll
    for (int n = 0; n < 8; ++n)
#pragma unroll
        for (int q = 0; q < 4; ++q) acc[n][q] = 0.f;

    stage(0, 0);
    for (int kc = 0; kc < 16; ++kc) {
        CPA_WAIT(0);
        __syncthreads();
        if (kc < 15) stage(kc + 1, (kc + 1) & 1);

        const uint32_t bb = sbase + (kc & 1) * PBUF;
        const uint32_t Xh = bb + P_XH, Xl = bb + P_XL;
        const uint32_t Wh = bb + P_WH, Wl = bb + P_WL;
        const int ra = wid * 16;

#pragma unroll
        for (int ks = 0; ks < 4; ++ks) {
            uint32_t ah[4], al[4];
            ldsm_x4(ah[0], ah[1], ah[2], ah[3], Xh + ra * RS + ks * 32 + aoff);
            ldsm_x4(al[0], al[1], al[2], al[3], Xl + ra * RS + ks * 32 + aoff);
#pragma unroll
            for (int p = 0; p < 4; ++p) {
                uint32_t h0, h1, h2, h3, l0, l1, l2, l3;
                ldsm_x4(h0, h1, h2, h3, Wh + p * 16 * RS + ks * 32 + boff);
                ldsm_x4(l0, l1, l2, l3, Wl + p * 16 * RS + ks * 32 + boff);
                mma_bf16(acc[2*p],   ah, h0, h1);
                mma_bf16(acc[2*p],   al, h0, h1);
                mma_bf16(acc[2*p],   ah, l0, l1);
                mma_bf16(acc[2*p+1], ah, h2, h3);
                mma_bf16(acc[2*p+1], al, h2, h3);
                mma_bf16(acc[2*p+1], ah, l2, l3);
            }
        }
        __syncthreads();
    }

    // epilogue
    const int rA = m0 + wid * 16 + g;
    const int rB = rA + 8;
#pragma unroll
    for (int n = 0; n < 8; ++n) {
        const int col = 8 * n + 2 * tg;
        float v0 = acc[n][0] + s_bias[col];
        float v1 = acc[n][1] + s_bias[col + 1];
        float v2 = acc[n][2] + s_bias[col];
        float v3 = acc[n][3] + s_bias[col + 1];
        if (my < 2) {
            uint32_t h01, l01, h23, l23;
            split_pair(v0, v1, h01, l01);
            split_pair(v2, v3, h23, l23);
            __nv_bfloat16* oh = (my == 0) ? g_qh : g_kh;
            __nv_bfloat16* ol = (my == 0) ? g_ql : g_kl;
            *(uint32_t*)(oh + (size_t)rA * 64 + col) = h01;
            *(uint32_t*)(ol + (size_t)rA * 64 + col) = l01;
            *(uint32_t*)(oh + (size_t)rB * 64 + col) = h23;
            *(uint32_t*)(ol + (size_t)rB * 64 + col) = l23;
        } else {
            const int bA = rA >> 12, tA = rA & 4095;
            const int bB = rB >> 12, tB = rB & 4095;
            __nv_bfloat16 h;
            h = __float2bfloat16_rn(v0);
            g_vth[(size_t)(bA*64 + col  )*4096 + tA] = h;
            g_vtl[(size_t)(bA*64 + col  )*4096 + tA] = __float2bfloat16_rn(v0 - __bfloat162float(h));
            h = __float2bfloat16_rn(v1);
            g_vth[(size_t)(bA*64 + col+1)*4096 + tA] = h;
            g_vtl[(size_t)(bA*64 + col+1)*4096 + tA] = __float2bfloat16_rn(v1 - __bfloat162float(h));
            h = __float2bfloat16_rn(v2);
            g_vth[(size_t)(bB*64 + col  )*4096 + tB] = h;
            g_vtl[(size_t)(bB*64 + col  )*4096 + tB] = __float2bfloat16_rn(v2 - __bfloat162float(h));
            h = __float2bfloat16_rn(v3);
            g_vth[(size_t)(bB*64 + col+1)*4096 + tB] = h;
            g_vtl[(size_t)(bB*64 + col+1)*4096 + tB] = __float2bfloat16_rn(v3 - __bfloat162float(h));
        }
    }
}

// ============================================================================
// Attention, chunk = 8 j-tiles: grid = 4 x 288; CTA = 128 thr, 3 CTAs/SM.
// Split-phase prefetch: Q(jt+1) issued right after S-phase reads Q(jt);
// V(jt+1) issued after PV reads V(jt). wait_group 1 leaves younger group
// in flight -> staging latency hidden inside the same (single) buffer.
// ============================================================================
#define K_REG   (2*64*RS)               // 18432: Kh, Kl
#define QV_BUF  (4*64*RS)               // 36864: Qh, Ql, Vh, Vl
#define ATTN_SMEM (K_REG + QV_BUF)      // 55296

__global__ __launch_bounds__(128, 3) void attn_kernel()
{
    extern __shared__ char smp[];
    const uint32_t sbase = smem_u32(smp);
    const int tid = threadIdx.x;
    const int lw  = tid >> 5;
    const int lane = tid & 31;
    const int g  = lane >> 2, tg = lane & 3;

    const int b   = blockIdx.x & 3;
    const int cid = 287 - (blockIdx.x >> 2);
    const int t = (cid >= 224) ? 7 : (cid >= 168) ? 6 : (cid >= 120) ? 5 :
                  (cid >= 80)  ? 4 : (cid >= 48)  ? 3 : (cid >= 24)  ? 2 :
                  (cid >= 8)   ? 1 : 0;
    const int off = cid - 4 * t * (t + 1);
    const int rb  = 8 * t + off / (t + 1);
    const int jc  = off % (t + 1);
    const int jt0 = jc * 8;
    const int jt1 = min(jt0 + 8, rb + 1);
    const int i0  = rb * 64;

    const uint32_t Kb = sbase;            // Kh at 0, Kl at +64*RS
    const uint32_t Qb = sbase + K_REG;    // Qh, Ql
    const uint32_t Vb = Qb + 2 * 64 * RS; // Vh, Vl

    // group 0: K tile
#pragma unroll
    for (int i = tid; i < 1024; i += 128) {
        const int comp = i >> 9;
        const int idx = i & 511;
        const int r = idx >> 3, c8 = idx & 7;
        const __nv_bfloat16* gsrc = comp ? g_kl : g_kh;
        cpa16(Kb + comp * (64 * RS) + r * RS + c8 * 16,
              gsrc + (size_t)(b * 4096 + i0 + r) * 64 + c8 * 8);
    }
    CPA_COMMIT();

    auto stageQ = [&](int jt) {
        const int j0 = jt * 64;
#pragma unroll
        for (int i = tid; i < 1024; i += 128) {
            const int comp = i >> 9;
            const int idx = i & 511;
            const int r = idx >> 3, c8 = idx & 7;
            const __nv_bfloat16* gsrc = comp ? g_ql : g_qh;
            cpa16(Qb + comp * (64 * RS) + r * RS + c8 * 16,
                  gsrc + (size_t)(b * 4096 + j0 + r) * 64 + c8 * 8);
        }
        CPA_COMMIT();
    };
    auto stageV = [&](int jt) {
        const int j0 = jt * 64;
#pragma unroll
        for (int i = tid; i < 1024; i += 128) {
            const int comp = i >> 9;
            const int idx = i & 511;
            const int r = idx >> 3, c8 = idx & 7;
            const __nv_bfloat16* gsrc = comp ? g_vtl : g_vth;
            cpa16(Vb + comp * (64 * RS) + r * RS + c8 * 16,
                  gsrc + (size_t)(b * 64 + r) * 4096 + j0 + c8 * 8);
        }
        CPA_COMMIT();
    };

    const uint32_t aoff = (lane & 7) * RS + ((lane >> 3) & 1) * 8 * RS
                        + ((lane >> 4) & 1) * 16;
    const uint32_t boff = (lane & 7) * RS + ((lane >> 4) & 1) * 8 * RS
                        + ((lane >> 3) & 1) * 16;
    const int rowA = i0 + lw * 16 + g;

    float o[8][4];
#pragma unroll
    for (int n = 0; n < 8; ++n)
#pragma unroll
        for (int q = 0; q < 4; ++q) o[n][q] = 0.f;
    float ellA = 0.f, ellB = 0.f;

    stageQ(jt0);     // group 1
    stageV(jt0);     // group 2

    for (int jt = jt0; jt < jt1; ++jt) {
        const int j0 = jt * 64;
        const bool more = (jt + 1 < jt1);

        // wait for K (first iter) + Q(jt); V(jt) may still be in flight
        CPA_WAIT(1);
        __syncthreads();

        const uint32_t Qh = Qb, Ql = Qb + 64 * RS;
        const uint32_t Vh = Vb, Vl = Vb + 64 * RS;

        // ---- S = K . Q^T ----
        float s[8][4];
#pragma unroll
        for (int n = 0; n < 8; ++n)
#pragma unroll
            for (int q = 0; q < 4; ++q) s[n][q] = 0.f;

#pragma unroll
        for (int ks = 0; ks < 4; ++ks) {
            uint32_t kh[4], kl[4];
            ldsm_x4(kh[0], kh[1], kh[2], kh[3],
                    Kb + (lw * 16) * RS + ks * 32 + aoff);
            ldsm_x4(kl[0], kl[1], kl[2], kl[3],
                    Kb + 64 * RS + (lw * 16) * RS + ks * 32 + aoff);
#pragma unroll
            for (int p = 0; p < 4; ++p) {
                uint32_t h0, h1, h2, h3, l0, l1, l2, l3;
                ldsm_x4(h0, h1, h2, h3, Qh + p * 16 * RS + ks * 32 + boff);
                ldsm_x4(l0, l1, l2, l3, Ql + p * 16 * RS + ks * 32 + boff);
                mma_bf16(s[2*p],   kh, h0, h1);
                mma_bf16(s[2*p],   kl, h0, h1);
                mma_bf16(s[2*p],   kh, l0, l1);
                mma_bf16(s[2*p+1], kh, h2, h3);
                mma_bf16(s[2*p+1], kl, h2, h3);
                mma_bf16(s[2*p+1], kh, l2, l3);
            }
        }

        // all warps finished reading Q buffer -> safe to overwrite
        __syncthreads();
        if (more) stageQ(jt + 1);

        // ---- P = exp(S), mask, ell, pack (covers Q prefetch latency) ----
        uint32_t pha[4][4], pla[4][4];
        const bool diag = (jt == rb);
#pragma unroll
        for (int n = 0; n < 8; ++n) {
            float p0 = __expf(s[n][0]);
            float p1 = __expf(s[n][1]);
            float p2 = __expf(s[n][2]);
            float p3 = __expf(s[n][3]);
            if (diag) {
                const int col = j0 + 8 * n + 2 * tg;
                if (col     > rowA)     p0 = 0.f;
                if (col + 1 > rowA)     p1 = 0.f;
                if (col     > rowA + 8) p2 = 0.f;
                if (col + 1 > rowA + 8) p3 = 0.f;
            }
            ellA += p0 + p1;
            ellB += p2 + p3;
            uint32_t h01, l01, h23, l23;
            split_pair(p0, p1, h01, l01);
            split_pair(p2, p3, h23, l23);
            const int tt = n >> 1;
            if ((n & 1) == 0) {
                pha[tt][0] = h01; pha[tt][1] = h23;
                pla[tt][0] = l01; pla[tt][1] = l23;
            } else {
                pha[tt][2] = h01; pha[tt][3] = h23;
                pla[tt][2] = l01; pla[tt][3] = l23;
            }
        }

        // wait for V(jt); Q(jt+1) (if any) stays in flight
        if (more) { CPA_WAIT(1); } else { CPA_WAIT(0); }
        __syncthreads();

        // ---- O += P . V ----
#pragma unroll
        for (int kt = 0; kt < 4; ++kt) {
#pragma unroll
            for (int p = 0; p < 4; ++p) {
                uint32_t h0, h1, h2, h3, l0, l1, l2, l3;
                ldsm_x4(h0, h1, h2, h3, Vh + p * 16 * RS + kt * 32 + boff);
                ldsm_x4(l0, l1, l2, l3, Vl + p * 16 * RS + kt * 32 + boff);
                mma_bf16(o[2*p],   pha[kt], h0, h1);
                mma_bf16(o[2*p],   pla[kt], h0, h1);
                mma_bf16(o[2*p],   pha[kt], l0, l1);
                mma_bf16(o[2*p+1], pha[kt], h2, h3);
                mma_bf16(o[2*p+1], pla[kt], h2, h3);
                mma_bf16(o[2*p+1], pha[kt], l2, l3);
            }
        }

        // all warps finished reading V buffer -> safe to overwrite
        __syncthreads();
        if (more) stageV(jt + 1);
    }

    // ---- epilogue: vector red accumulate O, scalar ell ----
    ellA += __shfl_xor_sync(0xffffffffu, ellA, 1);
    ellA += __shfl_xor_sync(0xffffffffu, ellA, 2);
    ellB += __shfl_xor_sync(0xffffffffu, ellB, 1);
    ellB += __shfl_xor_sync(0xffffffffu, ellB, 2);
    if (tg == 0) {
        atomicAdd(&g_ell[b * 4096 + rowA],     ellA);
        atomicAdd(&g_ell[b * 4096 + rowA + 8], ellB);
    }
    float* OA = g_O + (size_t)(b * 4096 + rowA) * 64;
    float* OB = OA + 8 * 64;
#pragma unroll
    for (int n = 0; n < 8; ++n) {
        const int col = 8 * n + 2 * tg;
        redg_v2(OA + col, o[n][0], o[n][1]);
        redg_v2(OB + col, o[n][2], o[n][3]);
    }
}

// ============================================================================
// Divide: out = O / ell
// ============================================================================
__global__ __launch_bounds__(256) void divide_kernel(float* __restrict__ out)
{
    const size_t tid0 = (size_t)blockIdx.x * 256 + threadIdx.x;
    const size_t stride = (size_t)gridDim.x * 256;
    const size_t N = (size_t)MROWS * HH / 4;
    for (size_t u = tid0; u < N; u += stride) {
        const size_t m = u >> 4;
        const float inv = 1.0f / g_ell[m];
        float4 v = ((const float4*)g_O)[u];
        v.x *= inv; v.y *= inv; v.z *= inv; v.w *= inv;
        ((float4*)out)[u] = v;
    }
}

// ============================================================================
extern "C" void kernel_launch(void* const* d_in, const int* in_sizes, int n_in,
                              void* d_out, int out_size)
{
    const float* x  = (const float*)d_in[0];
    const float* Wq = (const float*)d_in[1];
    const float* bq = (const float*)d_in[2];
    const float* Wk = (const float*)d_in[3];
    const float* bk = (const float*)d_in[4];
    const float* Wv = (const float*)d_in[5];
    const float* bv = (const float*)d_in[6];
    float* out = (float*)d_out;

    cudaFuncSetAttribute(proj_kernel, cudaFuncAttributeMaxDynamicSharedMemorySize, PROJ_SMEM);
    cudaFuncSetAttribute(attn_kernel, cudaFuncAttributeMaxDynamicSharedMemorySize, ATTN_SMEM);

    convert_kernel<<<1024, 256>>>(x, Wq, Wk, Wv);
    proj_kernel<<<dim3(128, 3), 256, PROJ_SMEM>>>(bq, bk, bv);
    attn_kernel<<<4 * 288, 128, ATTN_SMEM>>>();
    divide_kernel<<<1024, 256>>>(out);
}

// round 9
// speedup vs baseline: 4.5314x; 1.0057x over previous
#include <cuda_runtime.h>
#include <cuda_bf16.h>
#include <cstdint>

#define BB 4
#define TT 4096
#define DIN 1024
#define HH 64
#define MROWS (BB*TT)

// bf16 hi/lo split scratch
__device__ __nv_bfloat16 g_qh[(size_t)MROWS*HH], g_ql[(size_t)MROWS*HH];
__device__ __nv_bfloat16 g_kh[(size_t)MROWS*HH], g_kl[(size_t)MROWS*HH];
__device__ __nv_bfloat16 g_vth[(size_t)MROWS*HH], g_vtl[(size_t)MROWS*HH]; // [b][h][t]
// pre-converted inputs
__device__ __nv_bfloat16 g_xh[(size_t)MROWS*DIN], g_xl[(size_t)MROWS*DIN];
__device__ __nv_bfloat16 g_wh[3*HH*DIN], g_wl[3*HH*DIN];
// attention accumulators (fp32)
__device__ float g_O[(size_t)MROWS*HH];
__device__ float g_ell[MROWS];

// ---------------- helpers ----------------
__device__ __forceinline__ void mma_bf16(float* d, const uint32_t* a,
                                         uint32_t b0, uint32_t b1) {
    asm volatile(
        "mma.sync.aligned.m16n8k16.row.col.f32.bf16.bf16.f32 "
        "{%0,%1,%2,%3}, {%4,%5,%6,%7}, {%8,%9}, {%0,%1,%2,%3};"
        : "+f"(d[0]), "+f"(d[1]), "+f"(d[2]), "+f"(d[3])
        : "r"(a[0]), "r"(a[1]), "r"(a[2]), "r"(a[3]), "r"(b0), "r"(b1));
}

__device__ __forceinline__ void ldsm_x4(uint32_t& r0, uint32_t& r1,
                                        uint32_t& r2, uint32_t& r3, uint32_t a) {
    asm volatile("ldmatrix.sync.aligned.m8n8.x4.shared.b16 {%0,%1,%2,%3}, [%4];"
                 : "=r"(r0), "=r"(r1), "=r"(r2), "=r"(r3) : "r"(a));
}

__device__ __forceinline__ void split_pair(float x, float y,
                                           uint32_t& h, uint32_t& l) {
    __nv_bfloat162 hv = __floats2bfloat162_rn(x, y);
    float hx = __bfloat162float(hv.x);
    float hy = __bfloat162float(hv.y);
    __nv_bfloat162 lv = __floats2bfloat162_rn(x - hx, y - hy);
    h = *reinterpret_cast<uint32_t*>(&hv);
    l = *reinterpret_cast<uint32_t*>(&lv);
}

__device__ __forceinline__ uint32_t smem_u32(const void* p) {
    uint32_t a;
    asm("{ .reg .u64 t; cvta.to.shared.u64 t, %1; cvt.u32.u64 %0, t; }"
        : "=r"(a) : "l"(p));
    return a;
}

__device__ __forceinline__ void cpa16(uint32_t dst, const void* src) {
    asm volatile("cp.async.cg.shared.global [%0], [%1], 16;"
                 :: "r"(dst), "l"(src) : "memory");
}
#define CPA_COMMIT() asm volatile("cp.async.commit_group;" ::: "memory")
#define CPA_WAIT(N)  asm volatile("cp.async.wait_group %0;" :: "n"(N) : "memory")

__device__ __forceinline__ void redg_v2(float* p, float a, float b) {
    asm volatile("red.global.add.v2.f32 [%0], {%1, %2};"
                 :: "l"(p), "f"(a), "f"(b) : "memory");
}

#define RS 144   // smem row stride bytes

// ============================================================================
// Pre-convert + zero accumulators
// ============================================================================
__global__ __launch_bounds__(256) void convert_kernel(
    const float* __restrict__ x,
    const float* __restrict__ Wq, const float* __restrict__ Wk,
    const float* __restrict__ Wv)
{
    const size_t tid0 = (size_t)blockIdx.x * 256 + threadIdx.x;
    const size_t stride = (size_t)gridDim.x * 256;
    const size_t NX = (size_t)MROWS * DIN / 4;
    for (size_t t = tid0; t < NX; t += stride) {
        float4 v = ((const float4*)x)[t];
        uint32_t h0, l0, h1, l1;
        split_pair(v.x, v.y, h0, l0);
        split_pair(v.z, v.w, h1, l1);
        ((uint2*)g_xh)[t] = make_uint2(h0, h1);
        ((uint2*)g_xl)[t] = make_uint2(l0, l1);
    }
    const size_t NW = (size_t)HH * DIN / 4;
    for (size_t t = tid0; t < 3 * NW; t += stride) {
        const int set = (int)(t / NW);
        const size_t o = t - (size_t)set * NW;
        const float* W = (set == 0) ? Wq : (set == 1) ? Wk : Wv;
        float4 v = ((const float4*)W)[o];
        uint32_t h0, l0, h1, l1;
        split_pair(v.x, v.y, h0, l0);
        split_pair(v.z, v.w, h1, l1);
        ((uint2*)g_wh)[t] = make_uint2(h0, h1);
        ((uint2*)g_wl)[t] = make_uint2(l0, l1);
    }
    const float4 z4 = make_float4(0.f, 0.f, 0.f, 0.f);
    const size_t NO = (size_t)MROWS * HH / 4;
    for (size_t t = tid0; t < NO; t += stride) ((float4*)g_O)[t] = z4;
    for (size_t t = tid0; t < MROWS / 4; t += stride) ((float4*)g_ell)[t] = z4;
}

// ============================================================================
// Projection: grid=(128,3), 256 thr, 2 CTAs/SM, cp.async double buffer + ldsm.
// ============================================================================
#define P_XH 0
#define P_XL (128*RS)
#define P_WH (256*RS)
#define P_WL (256*RS + 64*RS)
#define PBUF (384*RS)
#define PROJ_SMEM (2*PBUF)

__global__ __launch_bounds__(256, 2) void proj_kernel(
    const float* __restrict__ bq, const float* __restrict__ bk,
    const float* __restrict__ bv)
{
    extern __shared__ char smp[];
    __shared__ float s_bias[64];
    const uint32_t sbase = smem_u32(smp);

    const int tid = threadIdx.x;
    const int wid = tid >> 5, lane = tid & 31;
    const int g = lane >> 2, tg = lane & 3;
    const int m0 = blockIdx.x * 128;
    const int my = blockIdx.y;

    const float* bias = (my == 0) ? bq : (my == 1) ? bk : bv;
    if (tid < 64) s_bias[tid] = bias[tid];

    const size_t wset = (size_t)my * HH * DIN;

    auto stage = [&](int kc, int bi) {
        const int k0 = kc * 64;
        const uint32_t bb = sbase + bi * PBUF;
#pragma unroll
        for (int u = tid; u < 3072; u += 256) {
            uint32_t dst; const void* src;
            if (u < 2048) {
                const int comp = u >> 10;
                const int idx = u & 1023;
                const int r = idx >> 3, c8 = idx & 7;
                const __nv_bfloat16* gsrc = comp ? g_xl : g_xh;
                src = gsrc + (size_t)(m0 + r) * DIN + k0 + c8 * 8;
                dst = bb + (comp ? P_XL : P_XH) + r * RS + c8 * 16;
            } else {
                const int comp = (u - 2048) >> 9;
                const int idx = (u - 2048) & 511;
                const int r = idx >> 3, c8 = idx & 7;
                const __nv_bfloat16* gsrc = comp ? g_wl : g_wh;
                src = gsrc + wset + (size_t)r * DIN + k0 + c8 * 8;
                dst = bb + (comp ? P_WL : P_WH) + r * RS + c8 * 16;
            }
            cpa16(dst, src);
        }
        CPA_COMMIT();
    };

    const uint32_t aoff = (lane & 7) * RS + ((lane >> 3) & 1) * 8 * RS
                        + ((lane >> 4) & 1) * 16;
    const uint32_t boff = (lane & 7) * RS + ((lane >> 4) & 1) * 8 * RS
                        + ((lane >> 3) & 1) * 16;

    float acc[8][4];
#pragma unroll
    for (int n = 0; n < 8; ++n)
#pragma unroll
        for (int q = 0; q < 4; ++q) acc[n][q] = 0.f;

    stage(0, 0);
    for (int kc = 0; kc < 16; ++kc) {
        CPA_WAIT(0);
        __syncthreads();
        if (kc < 15) stage(kc + 1, (kc + 1) & 1);

        const uint32_t bb = sbase + (kc & 1) * PBUF;
        const uint32_t Xh = bb + P_XH, Xl = bb + P_XL;
        const uint32_t Wh = bb + P_WH, Wl = bb + P_WL;
        const int ra = wid * 16;

#pragma unroll
        for (int ks = 0; ks < 4; ++ks) {
            uint32_t ah[4], al[4];
            ldsm_x4(ah[0], ah[1], ah[2], ah[3], Xh + ra * RS + ks * 32 + aoff);
            ldsm_x4(al[0], al[1], al[2], al[3], Xl + ra * RS + ks * 32 + aoff);
#pragma unroll
            for (int p = 0; p < 4; ++p) {
                uint32_t h0, h1, h2, h3, l0, l1, l2, l3;
                ldsm_x4(h0, h1, h2, h3, Wh + p * 16 * RS + ks * 32 + boff);
                ldsm_x4(l0, l1, l2, l3, Wl + p * 16 * RS + ks * 32 + boff);
                mma_bf16(acc[2*p],   ah, h0, h1);
                mma_bf16(acc[2*p],   al, h0, h1);
                mma_bf16(acc[2*p],   ah, l0, l1);
                mma_bf16(acc[2*p+1], ah, h2, h3);
                mma_bf16(acc[2*p+1], al, h2, h3);
                mma_bf16(acc[2*p+1], ah, l2, l3);
            }
        }
        __syncthreads();
    }

    // epilogue
    const int rA = m0 + wid * 16 + g;
    const int rB = rA + 8;
#pragma unroll
    for (int n = 0; n < 8; ++n) {
        const int col = 8 * n + 2 * tg;
        float v0 = acc[n][0] + s_bias[col];
        float v1 = acc[n][1] + s_bias[col + 1];
        float v2 = acc[n][2] + s_bias[col];
        float v3 = acc[n][3] + s_bias[col + 1];
        if (my < 2) {
            uint32_t h01, l01, h23, l23;
            split_pair(v0, v1, h01, l01);
            split_pair(v2, v3, h23, l23);
            __nv_bfloat16* oh = (my == 0) ? g_qh : g_kh;
            __nv_bfloat16* ol = (my == 0) ? g_ql : g_kl;
            *(uint32_t*)(oh + (size_t)rA * 64 + col) = h01;
            *(uint32_t*)(ol + (size_t)rA * 64 + col) = l01;
            *(uint32_t*)(oh + (size_t)rB * 64 + col) = h23;
            *(uint32_t*)(ol + (size_t)rB * 64 + col) = l23;
        } else {
            const int bA = rA >> 12, tA = rA & 4095;
            const int bB = rB >> 12, tB = rB & 4095;
            __nv_bfloat16 h;
            h = __float2bfloat16_rn(v0);
            g_vth[(size_t)(bA*64 + col  )*4096 + tA] = h;
            g_vtl[(size_t)(bA*64 + col  )*4096 + tA] = __float2bfloat16_rn(v0 - __bfloat162float(h));
            h = __float2bfloat16_rn(v1);
            g_vth[(size_t)(bA*64 + col+1)*4096 + tA] = h;
            g_vtl[(size_t)(bA*64 + col+1)*4096 + tA] = __float2bfloat16_rn(v1 - __bfloat162float(h));
            h = __float2bfloat16_rn(v2);
            g_vth[(size_t)(bB*64 + col  )*4096 + tB] = h;
            g_vtl[(size_t)(bB*64 + col  )*4096 + tB] = __float2bfloat16_rn(v2 - __bfloat162float(h));
            h = __float2bfloat16_rn(v3);
            g_vth[(size_t)(bB*64 + col+1)*4096 + tB] = h;
            g_vtl[(size_t)(bB*64 + col+1)*4096 + tB] = __float2bfloat16_rn(v3 - __bfloat162float(h));
        }
    }
}

// ============================================================================
// Attention, chunk = 8 j-tiles: grid = 4 x 288; CTA = 128 thr, 4 CTAs/SM.
// Fused exp->PV per kt (register diet + intra-warp pipe overlap).
// Split-phase Q/V prefetch retained.
// ============================================================================
#define K_REG   (2*64*RS)               // 18432: Kh, Kl
#define QV_BUF  (4*64*RS)               // 36864: Qh, Ql, Vh, Vl
#define ATTN_SMEM (K_REG + QV_BUF)      // 55296

__global__ __launch_bounds__(128, 4) void attn_kernel()
{
    extern __shared__ char smp[];
    const uint32_t sbase = smem_u32(smp);
    const int tid = threadIdx.x;
    const int lw  = tid >> 5;
    const int lane = tid & 31;
    const int g  = lane >> 2, tg = lane & 3;

    const int b   = blockIdx.x & 3;
    const int cid = 287 - (blockIdx.x >> 2);
    const int t = (cid >= 224) ? 7 : (cid >= 168) ? 6 : (cid >= 120) ? 5 :
                  (cid >= 80)  ? 4 : (cid >= 48)  ? 3 : (cid >= 24)  ? 2 :
                  (cid >= 8)   ? 1 : 0;
    const int off = cid - 4 * t * (t + 1);
    const int rb  = 8 * t + off / (t + 1);
    const int jc  = off % (t + 1);
    const int jt0 = jc * 8;
    const int jt1 = min(jt0 + 8, rb + 1);
    const int i0  = rb * 64;

    const uint32_t Kb = sbase;            // Kh at 0, Kl at +64*RS
    const uint32_t Qb = sbase + K_REG;    // Qh, Ql
    const uint32_t Vb = Qb + 2 * 64 * RS; // Vh, Vl

    // group 0: K tile
#pragma unroll
    for (int i = tid; i < 1024; i += 128) {
        const int comp = i >> 9;
        const int idx = i & 511;
        const int r = idx >> 3, c8 = idx & 7;
        const __nv_bfloat16* gsrc = comp ? g_kl : g_kh;
        cpa16(Kb + comp * (64 * RS) + r * RS + c8 * 16,
              gsrc + (size_t)(b * 4096 + i0 + r) * 64 + c8 * 8);
    }
    CPA_COMMIT();

    auto stageQ = [&](int jt) {
        const int j0 = jt * 64;
#pragma unroll
        for (int i = tid; i < 1024; i += 128) {
            const int comp = i >> 9;
            const int idx = i & 511;
            const int r = idx >> 3, c8 = idx & 7;
            const __nv_bfloat16* gsrc = comp ? g_ql : g_qh;
            cpa16(Qb + comp * (64 * RS) + r * RS + c8 * 16,
                  gsrc + (size_t)(b * 4096 + j0 + r) * 64 + c8 * 8);
        }
        CPA_COMMIT();
    };
    auto stageV = [&](int jt) {
        const int j0 = jt * 64;
#pragma unroll
        for (int i = tid; i < 1024; i += 128) {
            const int comp = i >> 9;
            const int idx = i & 511;
            const int r = idx >> 3, c8 = idx & 7;
            const __nv_bfloat16* gsrc = comp ? g_vtl : g_vth;
            cpa16(Vb + comp * (64 * RS) + r * RS + c8 * 16,
                  gsrc + (size_t)(b * 64 + r) * 4096 + j0 + c8 * 8);
        }
        CPA_COMMIT();
    };

    const uint32_t aoff = (lane & 7) * RS + ((lane >> 3) & 1) * 8 * RS
                        + ((lane >> 4) & 1) * 16;
    const uint32_t boff = (lane & 7) * RS + ((lane >> 4) & 1) * 8 * RS
                        + ((lane >> 3) & 1) * 16;
    const int rowA = i0 + lw * 16 + g;

    float o[8][4];
#pragma unroll
    for (int n = 0; n < 8; ++n)
#pragma unroll
        for (int q = 0; q < 4; ++q) o[n][q] = 0.f;
    float ellA = 0.f, ellB = 0.f;

    stageQ(jt0);     // group 1
    stageV(jt0);     // group 2

    for (int jt = jt0; jt < jt1; ++jt) {
        const int j0 = jt * 64;
        const bool more = (jt + 1 < jt1);

        // wait for K (first iter) + Q(jt); V(jt) may still be in flight
        CPA_WAIT(1);
        __syncthreads();

        const uint32_t Qh = Qb, Ql = Qb + 64 * RS;
        const uint32_t Vh = Vb, Vl = Vb + 64 * RS;

        // ---- S = K . Q^T ----
        float s[8][4];
#pragma unroll
        for (int n = 0; n < 8; ++n)
#pragma unroll
            for (int q = 0; q < 4; ++q) s[n][q] = 0.f;

#pragma unroll
        for (int ks = 0; ks < 4; ++ks) {
            uint32_t kh[4], kl[4];
            ldsm_x4(kh[0], kh[1], kh[2], kh[3],
                    Kb + (lw * 16) * RS + ks * 32 + aoff);
            ldsm_x4(kl[0], kl[1], kl[2], kl[3],
                    Kb + 64 * RS + (lw * 16) * RS + ks * 32 + aoff);
#pragma unroll
            for (int p = 0; p < 4; ++p) {
                uint32_t h0, h1, h2, h3, l0, l1, l2, l3;
                ldsm_x4(h0, h1, h2, h3, Qh + p * 16 * RS + ks * 32 + boff);
                ldsm_x4(l0, l1, l2, l3, Ql + p * 16 * RS + ks * 32 + boff);
                mma_bf16(s[2*p],   kh, h0, h1);
                mma_bf16(s[2*p],   kl, h0, h1);
                mma_bf16(s[2*p],   kh, l0, l1);
                mma_bf16(s[2*p+1], kh, h2, h3);
                mma_bf16(s[2*p+1], kl, h2, h3);
                mma_bf16(s[2*p+1], kh, l2, l3);
            }
        }

        // all warps finished reading Q buffer -> safe to overwrite
        __syncthreads();
        if (more) stageQ(jt + 1);

        // wait for V(jt); Q(jt+1) (if any) stays in flight
        if (more) { CPA_WAIT(1); } else { CPA_WAIT(0); }
        __syncthreads();

        // ---- fused: per kt: exp(S) -> pack -> O += P_kt . V_kt ----
        const bool diag = (jt == rb);
#pragma unroll
        for (int kt = 0; kt < 4; ++kt) {
            uint32_t pha[4], pla[4];
#pragma unroll
            for (int h = 0; h < 2; ++h) {
                const int n = 2 * kt + h;
                float p0 = __expf(s[n][0]);
                float p1 = __expf(s[n][1]);
                float p2 = __expf(s[n][2]);
                float p3 = __expf(s[n][3]);
                if (diag) {
                    const int col = j0 + 8 * n + 2 * tg;
                    if (col     > rowA)     p0 = 0.f;
                    if (col + 1 > rowA)     p1 = 0.f;
                    if (col     > rowA + 8) p2 = 0.f;
                    if (col + 1 > rowA + 8) p3 = 0.f;
                }
                ellA += p0 + p1;
                ellB += p2 + p3;
                uint32_t h01, l01, h23, l23;
                split_pair(p0, p1, h01, l01);
                split_pair(p2, p3, h23, l23);
                if (h == 0) {
                    pha[0] = h01; pha[1] = h23;
                    pla[0] = l01; pla[1] = l23;
                } else {
                    pha[2] = h01; pha[3] = h23;
                    pla[2] = l01; pla[3] = l23;
                }
            }
#pragma unroll
            for (int p = 0; p < 4; ++p) {
                uint32_t h0, h1, h2, h3, l0, l1, l2, l3;
                ldsm_x4(h0, h1, h2, h3, Vh + p * 16 * RS + kt * 32 + boff);
                ldsm_x4(l0, l1, l2, l3, Vl + p * 16 * RS + kt * 32 + boff);
                mma_bf16(o[2*p],   pha, h0, h1);
                mma_bf16(o[2*p],   pla, h0, h1);
                mma_bf16(o[2*p],   pha, l0, l1);
                mma_bf16(o[2*p+1], pha, h2, h3);
                mma_bf16(o[2*p+1], pla, h2, h3);
                mma_bf16(o[2*p+1], pha, l2, l3);
            }
        }

        // all warps finished reading V buffer -> safe to overwrite
        __syncthreads();
        if (more) stageV(jt + 1);
    }

    // ---- epilogue: vector red accumulate O, scalar ell ----
    ellA += __shfl_xor_sync(0xffffffffu, ellA, 1);
    ellA += __shfl_xor_sync(0xffffffffu, ellA, 2);
    ellB += __shfl_xor_sync(0xffffffffu, ellB, 1);
    ellB += __shfl_xor_sync(0xffffffffu, ellB, 2);
    if (tg == 0) {
        atomicAdd(&g_ell[b * 4096 + rowA],     ellA);
        atomicAdd(&g_ell[b * 4096 + rowA + 8], ellB);
    }
    float* OA = g_O + (size_t)(b * 4096 + rowA) * 64;
    float* OB = OA + 8 * 64;
#pragma unroll
    for (int n = 0; n < 8; ++n) {
        const int col = 8 * n + 2 * tg;
        redg_v2(OA + col, o[n][0], o[n][1]);
        redg_v2(OB + col, o[n][2], o[n][3]);
    }
}

// ============================================================================
// Divide: out = O / ell
// ============================================================================
__global__ __launch_bounds__(256) void divide_kernel(float* __restrict__ out)
{
    const size_t tid0 = (size_t)blockIdx.x * 256 + threadIdx.x;
    const size_t stride = (size_t)gridDim.x * 256;
    const size_t N = (size_t)MROWS * HH / 4;
    for (size_t u = tid0; u < N; u += stride) {
        const size_t m = u >> 4;
        const float inv = 1.0f / g_ell[m];
        float4 v = ((const float4*)g_O)[u];
        v.x *= inv; v.y *= inv; v.z *= inv; v.w *= inv;
        ((float4*)out)[u] = v;
    }
}

// ============================================================================
extern "C" void kernel_launch(void* const* d_in, const int* in_sizes, int n_in,
                              void* d_out, int out_size)
{
    const float* x  = (const float*)d_in[0];
    const float* Wq = (const float*)d_in[1];
    const float* bq = (const float*)d_in[2];
    const float* Wk = (const float*)d_in[3];
    const float* bk = (const float*)d_in[4];
    const float* Wv = (const float*)d_in[5];
    const float* bv = (const float*)d_in[6];
    float* out = (float*)d_out;

    cudaFuncSetAttribute(proj_kernel, cudaFuncAttributeMaxDynamicSharedMemorySize, PROJ_SMEM);
    cudaFuncSetAttribute(attn_kernel, cudaFuncAttributeMaxDynamicSharedMemorySize, ATTN_SMEM);

    convert_kernel<<<1024, 256>>>(x, Wq, Wk, Wv);
    proj_kernel<<<dim3(128, 3), 256, PROJ_SMEM>>>(bq, bk, bv);
    attn_kernel<<<4 * 288, 128, ATTN_SMEM>>>();
    divide_kernel<<<1024, 256>>>(out);
}